// round 8
// baseline (speedup 1.0000x reference)
#include <cuda_runtime.h>
#include <cuda_fp16.h>
#include <cstdint>
#include <math.h>

#define NB 32
#define NS 1024
#define NH 1024
#define ND 128

// persistent scratch (__device__ globals per allocation rules) — split fp16
__device__ __half g_xh[NB * NS * NH];
__device__ __half g_xl[NB * NS * NH];
__device__ __half g_qh[NB * NS * ND];
__device__ __half g_ql[NB * NS * ND];
__device__ __half g_kh[NB * NS * ND];
__device__ __half g_kl[NB * NS * ND];
__device__ __half g_vh[NB * NS * ND];
__device__ __half g_vl[NB * NS * ND];
__device__ __half g_ph[NB * NS * NS];   // split normalized probs
__device__ __half g_pl[NB * NS * NS];
__device__ __half g_wthi[3 * ND * NH];  // [w][n][k]
__device__ __half g_wtlo[3 * ND * NH];

// ---------------------------------------------------------------------------
// helpers
// ---------------------------------------------------------------------------
__device__ __forceinline__ uint32_t smem_u32(const void* p) {
    uint32_t a;
    asm("{ .reg .u64 t; cvta.to.shared.u64 t, %1; cvt.u32.u64 %0, t; }" : "=r"(a) : "l"(p));
    return a;
}
__device__ __forceinline__ void ldsm_x4(uint32_t* r, uint32_t addr) {
    asm volatile("ldmatrix.sync.aligned.m8n8.x4.shared.b16 {%0,%1,%2,%3}, [%4];"
                 : "=r"(r[0]), "=r"(r[1]), "=r"(r[2]), "=r"(r[3]) : "r"(addr));
}
__device__ __forceinline__ void ldsm_x4_t(uint32_t* r, uint32_t addr) {
    asm volatile("ldmatrix.sync.aligned.m8n8.x4.trans.shared.b16 {%0,%1,%2,%3}, [%4];"
                 : "=r"(r[0]), "=r"(r[1]), "=r"(r[2]), "=r"(r[3]) : "r"(addr));
}
// main term: fp16 inputs, fp32 accumulate
__device__ __forceinline__ void mma_f32(float* d, const uint32_t* a, const uint32_t* b) {
    asm volatile(
        "mma.sync.aligned.m16n8k16.row.col.f32.f16.f16.f32 "
        "{%0,%1,%2,%3}, {%4,%5,%6,%7}, {%8,%9}, {%0,%1,%2,%3};"
        : "+f"(d[0]), "+f"(d[1]), "+f"(d[2]), "+f"(d[3])
        : "r"(a[0]), "r"(a[1]), "r"(a[2]), "r"(a[3]), "r"(b[0]), "r"(b[1]));
}
// correction terms: fp16 accumulate (hypothesis: 2x rate)
__device__ __forceinline__ void mma_f16(uint32_t* d, const uint32_t* a, const uint32_t* b) {
    asm volatile(
        "mma.sync.aligned.m16n8k16.row.col.f16.f16.f16.f16 "
        "{%0,%1}, {%2,%3,%4,%5}, {%6,%7}, {%0,%1};"
        : "+r"(d[0]), "+r"(d[1])
        : "r"(a[0]), "r"(a[1]), "r"(a[2]), "r"(a[3]), "r"(b[0]), "r"(b[1]));
}
__device__ __forceinline__ void add_corr(float* acc, const uint32_t* c) {
    float2 f0 = __half22float2(*(const __half2*)&c[0]);
    float2 f1 = __half22float2(*(const __half2*)&c[1]);
    acc[0] += f0.x; acc[1] += f0.y; acc[2] += f1.x; acc[3] += f1.y;
}
__device__ __forceinline__ void split2(float a, float b, uint32_t& hi, uint32_t& lo) {
    __half ha = __float2half_rn(a), hb = __float2half_rn(b);
    __half la = __float2half_rn(a - __half2float(ha));
    __half lb = __float2half_rn(b - __half2float(hb));
    hi = (uint32_t)__half_as_ushort(ha) | ((uint32_t)__half_as_ushort(hb) << 16);
    lo = (uint32_t)__half_as_ushort(la) | ((uint32_t)__half_as_ushort(lb) << 16);
}
__device__ __forceinline__ float fast_exp(float x) {
    float t = x * 1.4426950408889634f;
    int ii = __float2int_rn(t);
    float f = t - (float)ii;
    float y = f * 0.6931471805599453f;
    float p = 1.0f + y * (1.0f + y * (0.5f + y * (0.16666667f + y * (0.041666668f + y * 0.008333334f))));
    return __int_as_float(__float_as_int(p) + (ii << 23));
}
__device__ __forceinline__ void cp_async16(uint32_t smem_addr, const void* gptr) {
    asm volatile("cp.async.cg.shared.global [%0], [%1], 16;" :: "r"(smem_addr), "l"(gptr));
}
#define CP_COMMIT() asm volatile("cp.async.commit_group;" ::: "memory")
#define CP_WAIT(n)  asm volatile("cp.async.wait_group %0;" :: "n"(n) : "memory")

// ---------------------------------------------------------------------------
// X split
// ---------------------------------------------------------------------------
__global__ __launch_bounds__(256) void convx_kernel(const float* __restrict__ X)
{
    const int total = NB * NS * NH / 4;
    for (int i = blockIdx.x * 256 + threadIdx.x; i < total; i += gridDim.x * 256) {
        float4 v = ((const float4*)X)[i];
        uint2 h, l;
        split2(v.x, v.y, h.x, l.x);
        split2(v.z, v.w, h.y, l.y);
        ((uint2*)g_xh)[i] = h;
        ((uint2*)g_xl)[i] = l;
    }
}

// ---------------------------------------------------------------------------
// Weight transpose+split
// ---------------------------------------------------------------------------
__global__ __launch_bounds__(256) void convw_kernel(
    const float* __restrict__ Wq, const float* __restrict__ Wk, const float* __restrict__ Wv)
{
    __shared__ float sW[64 * 129];
    int w = blockIdx.x >> 4;
    int k0 = (blockIdx.x & 15) * 64;
    const float* W = (w == 0) ? Wq : (w == 1) ? Wk : Wv;
    int tid = threadIdx.x;

    #pragma unroll
    for (int it = 0; it < 32; it++) {
        int f = tid + it * 256;
        int kk = f >> 7, n = f & 127;
        sW[kk * 129 + n] = W[(size_t)(k0 + kk) * ND + n];
    }
    __syncthreads();

    #pragma unroll
    for (int it = 0; it < 32; it++) {
        int f = tid + it * 256;
        int n = f >> 6, kk = f & 63;
        float x = sW[kk * 129 + n];
        __half hi = __float2half_rn(x);
        __half lo = __float2half_rn(x - __half2float(hi));
        size_t di = (size_t)w * ND * NH + (size_t)n * NH + k0 + kk;
        g_wthi[di] = hi;
        g_wtlo[di] = lo;
    }
}

// ---------------------------------------------------------------------------
// QKV GEMM: BM=128 BN=128 BK=32, 512 threads (16 warps 4x4, warp 32x32).
// main f32-accum MMA + corrections in fp16-accum MMA.
// ---------------------------------------------------------------------------
#define TSTRIDE 40
#define QK_AHI 0
#define QK_ALO 10240
#define QK_BHI 20480
#define QK_BLO 30720
#define QK_STAGE 40960
#define QK_SMEM (2 * QK_STAGE)

__global__ __launch_bounds__(512, 1) void qkv_mma_kernel(
    const float* __restrict__ bq, const float* __restrict__ bk, const float* __restrict__ bv)
{
    extern __shared__ char sm[];
    const uint32_t uS = smem_u32(sm);

    const int tid = threadIdx.x;
    const int wid = tid >> 5, lid = tid & 31;
    const int m0 = blockIdx.x * 128;
    const int w  = blockIdx.y;

    const __half* Whi = g_wthi + (size_t)w * ND * NH;
    const __half* Wlo = g_wtlo + (size_t)w * ND * NH;
    const float* bias = (w == 0) ? bq : (w == 1) ? bk : bv;
    __half* outh = (w == 0) ? g_qh : (w == 1) ? g_kh : g_vh;
    __half* outl = (w == 0) ? g_ql : (w == 1) ? g_kl : g_vl;
    const float oscale = (w == 0) ? 0.08838834764831845f : 1.0f;

    const int warpM = (wid >> 2) * 32;   // 0,32,64,96
    const int warpN = (wid & 3) * 32;    // 0,32,64,96

    const int a_row  = lid & 15;
    const int a_koff = (lid >> 4) * 8;
    const int bx_row  = (lid & 7) + (lid >> 4) * 8;
    const int bx_koff = ((lid >> 3) & 1) * 8;

    float acc[2][4][4];
    uint32_t corr[2][4][2];
    #pragma unroll
    for (int i = 0; i < 2; i++)
        #pragma unroll
        for (int j = 0; j < 4; j++) {
            #pragma unroll
            for (int c = 0; c < 4; c++) acc[i][j][c] = 0.f;
            corr[i][j][0] = 0u; corr[i][j][1] = 0u;
        }

    auto issue_stage = [&](int kc, int s) {
        const int k0 = kc * 32;
        const uint32_t base = uS + s * QK_STAGE;
        #pragma unroll
        for (int it = 0; it < 2; it++) {
            int f = tid + it * 512;
            int arr = f >> 9, g = f & 511;
            int row = g >> 2, u = g & 3;
            const __half* src = (arr ? g_xl : g_xh) + (size_t)(m0 + row) * NH + k0 + u * 8;
            cp_async16(base + (arr ? QK_ALO : QK_AHI) + (uint32_t)(row * TSTRIDE + u * 8) * 2, src);
        }
        #pragma unroll
        for (int it = 0; it < 2; it++) {
            int f = tid + it * 512;
            int arr = f >> 9, g = f & 511;
            int row = g >> 2, u = g & 3;
            const __half* src = (arr ? Wlo : Whi) + (size_t)row * NH + k0 + u * 8;
            cp_async16(base + (arr ? QK_BLO : QK_BHI) + (uint32_t)(row * TSTRIDE + u * 8) * 2, src);
        }
        CP_COMMIT();
    };

    issue_stage(0, 0);

    for (int kc = 0; kc < 32; kc++) {
        if (kc < 31) { issue_stage(kc + 1, (kc + 1) & 1); CP_WAIT(1); }
        else         { CP_WAIT(0); }
        __syncthreads();

        const uint32_t base = uS + (kc & 1) * QK_STAGE;
        #pragma unroll
        for (int ks = 0; ks < 2; ks++) {
            uint32_t ahi[2][4], alo[2][4];
            #pragma unroll
            for (int mi = 0; mi < 2; mi++) {
                uint32_t off = ((warpM + mi * 16 + a_row) * TSTRIDE + ks * 16 + a_koff) * 2;
                ldsm_x4(ahi[mi], base + QK_AHI + off);
                ldsm_x4(alo[mi], base + QK_ALO + off);
            }
            #pragma unroll
            for (int njp = 0; njp < 2; njp++) {
                uint32_t boff = ((warpN + njp * 16 + bx_row) * TSTRIDE + ks * 16 + bx_koff) * 2;
                uint32_t bh[4], bl[4];
                ldsm_x4(bh, base + QK_BHI + boff);
                ldsm_x4(bl, base + QK_BLO + boff);
                #pragma unroll
                for (int h = 0; h < 2; h++)
                    #pragma unroll
                    for (int mi = 0; mi < 2; mi++)
                        mma_f32(acc[mi][njp * 2 + h], ahi[mi], &bh[h * 2]);
                #pragma unroll
                for (int h = 0; h < 2; h++)
                    #pragma unroll
                    for (int mi = 0; mi < 2; mi++)
                        mma_f16(corr[mi][njp * 2 + h], ahi[mi], &bl[h * 2]);
                #pragma unroll
                for (int h = 0; h < 2; h++)
                    #pragma unroll
                    for (int mi = 0; mi < 2; mi++)
                        mma_f16(corr[mi][njp * 2 + h], alo[mi], &bh[h * 2]);
            }
        }
        __syncthreads();
    }

    #pragma unroll
    for (int mi = 0; mi < 2; mi++) {
        #pragma unroll
        for (int nj = 0; nj < 4; nj++) {
            add_corr(acc[mi][nj], corr[mi][nj]);
            int r0 = m0 + warpM + mi * 16 + (lid >> 2);
            int c0 = warpN + nj * 8 + (lid & 3) * 2;
            float b0 = bias[c0], b1 = bias[c0 + 1];
            float v0 = (acc[mi][nj][0] + b0) * oscale;
            float v1 = (acc[mi][nj][1] + b1) * oscale;
            float v2 = (acc[mi][nj][2] + b0) * oscale;
            float v3 = (acc[mi][nj][3] + b1) * oscale;
            uint32_t h01, l01, h23, l23;
            split2(v0, v1, h01, l01);
            split2(v2, v3, h23, l23);
            *(uint32_t*)&outh[(size_t)r0 * ND + c0] = h01;
            *(uint32_t*)&outl[(size_t)r0 * ND + c0] = l01;
            *(uint32_t*)&outh[(size_t)(r0 + 8) * ND + c0] = h23;
            *(uint32_t*)&outl[(size_t)(r0 + 8) * ND + c0] = l23;
        }
    }
}

// ---------------------------------------------------------------------------
// score_kernel: raw S = q_scaled @ k^T -> probs buffer (fp32).
// 512 threads, warp 32x32, grid(8,8,32).
// ---------------------------------------------------------------------------
__global__ __launch_bounds__(512, 1) void score_kernel(float* __restrict__ probs)
{
    extern __shared__ char sm[];
    const uint32_t uS = smem_u32(sm);

    const int tid = threadIdx.x;
    const int wid = tid >> 5, lid = tid & 31;
    const int m0 = blockIdx.x * 128;
    const int n0 = blockIdx.y * 128;
    const int b  = blockIdx.z;
    const size_t qbase = (size_t)(b * NS + m0) * ND;
    const size_t kbase = (size_t)(b * NS + n0) * ND;

    const int warpM = (wid >> 2) * 32;
    const int warpN = (wid & 3) * 32;
    const int a_row  = lid & 15;
    const int a_koff = (lid >> 4) * 8;
    const int bx_row  = (lid & 7) + (lid >> 4) * 8;
    const int bx_koff = ((lid >> 3) & 1) * 8;

    float acc[2][4][4];
    uint32_t corr[2][4][2];
    #pragma unroll
    for (int i = 0; i < 2; i++)
        #pragma unroll
        for (int j = 0; j < 4; j++) {
            #pragma unroll
            for (int c = 0; c < 4; c++) acc[i][j][c] = 0.f;
            corr[i][j][0] = 0u; corr[i][j][1] = 0u;
        }

    auto issue_stage = [&](int kc, int s) {
        const int k0 = kc * 32;
        const uint32_t base = uS + s * QK_STAGE;
        #pragma unroll
        for (int it = 0; it < 2; it++) {
            int f = tid + it * 512;
            int arr = f >> 9, g = f & 511;
            int row = g >> 2, u = g & 3;
            const __half* src = (arr ? g_ql : g_qh) + qbase + (size_t)row * ND + k0 + u * 8;
            cp_async16(base + (arr ? QK_ALO : QK_AHI) + (uint32_t)(row * TSTRIDE + u * 8) * 2, src);
        }
        #pragma unroll
        for (int it = 0; it < 2; it++) {
            int f = tid + it * 512;
            int arr = f >> 9, g = f & 511;
            int row = g >> 2, u = g & 3;
            const __half* src = (arr ? g_kl : g_kh) + kbase + (size_t)row * ND + k0 + u * 8;
            cp_async16(base + (arr ? QK_BLO : QK_BHI) + (uint32_t)(row * TSTRIDE + u * 8) * 2, src);
        }
        CP_COMMIT();
    };

    issue_stage(0, 0);

    for (int kc = 0; kc < 4; kc++) {
        if (kc < 3) { issue_stage(kc + 1, (kc + 1) & 1); CP_WAIT(1); }
        else        { CP_WAIT(0); }
        __syncthreads();

        const uint32_t base = uS + (kc & 1) * QK_STAGE;
        #pragma unroll
        for (int ks = 0; ks < 2; ks++) {
            uint32_t ahi[2][4], alo[2][4];
            #pragma unroll
            for (int mi = 0; mi < 2; mi++) {
                uint32_t off = ((warpM + mi * 16 + a_row) * TSTRIDE + ks * 16 + a_koff) * 2;
                ldsm_x4(ahi[mi], base + QK_AHI + off);
                ldsm_x4(alo[mi], base + QK_ALO + off);
            }
            #pragma unroll
            for (int njp = 0; njp < 2; njp++) {
                uint32_t boff = ((warpN + njp * 16 + bx_row) * TSTRIDE + ks * 16 + bx_koff) * 2;
                uint32_t bh[4], bl[4];
                ldsm_x4(bh, base + QK_BHI + boff);
                ldsm_x4(bl, base + QK_BLO + boff);
                #pragma unroll
                for (int h = 0; h < 2; h++)
                    #pragma unroll
                    for (int mi = 0; mi < 2; mi++)
                        mma_f32(acc[mi][njp * 2 + h], ahi[mi], &bh[h * 2]);
                #pragma unroll
                for (int h = 0; h < 2; h++)
                    #pragma unroll
                    for (int mi = 0; mi < 2; mi++)
                        mma_f16(corr[mi][njp * 2 + h], ahi[mi], &bl[h * 2]);
                #pragma unroll
                for (int h = 0; h < 2; h++)
                    #pragma unroll
                    for (int mi = 0; mi < 2; mi++)
                        mma_f16(corr[mi][njp * 2 + h], alo[mi], &bh[h * 2]);
            }
        }
        __syncthreads();
    }

    float* pb = probs + (size_t)b * NS * NS;
    #pragma unroll
    for (int mi = 0; mi < 2; mi++) {
        #pragma unroll
        for (int nj = 0; nj < 4; nj++) {
            add_corr(acc[mi][nj], corr[mi][nj]);
            int r0 = m0 + warpM + mi * 16 + (lid >> 2);
            int c0 = n0 + warpN + nj * 8 + (lid & 3) * 2;
            *(float2*)&pb[(size_t)r0 * NS + c0]       = make_float2(acc[mi][nj][0], acc[mi][nj][1]);
            *(float2*)&pb[(size_t)(r0 + 8) * NS + c0] = make_float2(acc[mi][nj][2], acc[mi][nj][3]);
        }
    }
}

// ---------------------------------------------------------------------------
// softmax_kernel: warp per row, register resident; writes fp16 split P.
// ---------------------------------------------------------------------------
__global__ __launch_bounds__(256) void softmax_kernel(float* __restrict__ probs)
{
    const int wid = threadIdx.x >> 5, lid = threadIdx.x & 31;
    const int row = blockIdx.x * 8 + wid;
    const size_t base4 = (size_t)row * (NS / 4);

    float4 v[8];
    #pragma unroll
    for (int u = 0; u < 8; u++) v[u] = ((const float4*)probs)[base4 + lid + u * 32];

    float mx = -1e30f;
    #pragma unroll
    for (int u = 0; u < 8; u++) {
        mx = fmaxf(mx, fmaxf(fmaxf(v[u].x, v[u].y), fmaxf(v[u].z, v[u].w)));
    }
    #pragma unroll
    for (int o = 1; o < 32; o <<= 1) mx = fmaxf(mx, __shfl_xor_sync(0xffffffffu, mx, o));

    float sum = 0.f;
    #pragma unroll
    for (int u = 0; u < 8; u++) {
        v[u].x = fast_exp(v[u].x - mx);
        v[u].y = fast_exp(v[u].y - mx);
        v[u].z = fast_exp(v[u].z - mx);
        v[u].w = fast_exp(v[u].w - mx);
        sum += (v[u].x + v[u].y) + (v[u].z + v[u].w);
    }
    #pragma unroll
    for (int o = 1; o < 32; o <<= 1) sum += __shfl_xor_sync(0xffffffffu, sum, o);
    const float inv = 1.f / sum;

    #pragma unroll
    for (int u = 0; u < 8; u++) {
        v[u].x *= inv; v[u].y *= inv; v[u].z *= inv; v[u].w *= inv;
        ((float4*)probs)[base4 + lid + u * 32] = v[u];
        uint2 h, l;
        split2(v[u].x, v[u].y, h.x, l.x);
        split2(v[u].z, v[u].w, h.y, l.y);
        ((uint2*)g_ph)[base4 + lid + u * 32] = h;
        ((uint2*)g_pl)[base4 + lid + u * 32] = l;
    }
}

// ---------------------------------------------------------------------------
// pv_kernel: O = P @ V. BM=64, grid(16,32)=512 CTAs, 256 threads (8 warps 2x4),
// warp tile 32x32, K=1024, BK=32, 2 CTAs/SM.
// ---------------------------------------------------------------------------
#define PV_PHI 0
#define PV_PLO 5120
#define PV_VHI 10240
#define PV_VLO 18944
#define PV_STAGE 27648
#define PV_SMEM (2 * PV_STAGE)
#define VSTRIDE 136

__global__ __launch_bounds__(256, 2) void pv_kernel(float* __restrict__ o_out)
{
    extern __shared__ char sm[];
    const uint32_t uS = smem_u32(sm);

    const int tid = threadIdx.x;
    const int wid = tid >> 5, lid = tid & 31;
    const int m0 = blockIdx.x * 64;
    const int b  = blockIdx.y;
    const size_t pbase = (size_t)(b * NS + m0) * NS;
    const size_t vbase = (size_t)(b * NS) * ND;

    const int warpM = (wid >> 2) * 32;   // 0,32
    const int warpN = (wid & 3) * 32;    // 0,32,64,96
    const int a_row  = lid & 15;
    const int a_koff = (lid >> 4) * 8;
    const int t_krow = (lid & 7) + ((lid >> 3) & 1) * 8;
    const int t_ncol = (lid >> 4) * 8;

    float acc[2][4][4];
    uint32_t corr[2][4][2];
    #pragma unroll
    for (int i = 0; i < 2; i++)
        #pragma unroll
        for (int j = 0; j < 4; j++) {
            #pragma unroll
            for (int c = 0; c < 4; c++) acc[i][j][c] = 0.f;
            corr[i][j][0] = 0u; corr[i][j][1] = 0u;
        }

    auto issue_stage = [&](int kc, int s) {
        const int k0 = kc * 32;
        const uint32_t base = uS + s * PV_STAGE;
        // P tile: 64 q-rows x 32 k (hi/lo): 2x256 uint4
        #pragma unroll
        for (int it = 0; it < 2; it++) {
            int f = tid + it * 256;
            int arr = f >> 8, g = f & 255;
            int row = g >> 2, u = g & 3;
            const __half* src = (arr ? g_pl : g_ph) + pbase + (size_t)row * NS + k0 + u * 8;
            cp_async16(base + (arr ? PV_PLO : PV_PHI) + (uint32_t)(row * TSTRIDE + u * 8) * 2, src);
        }
        // V tile: 32 k-rows x 128 d (hi/lo): 2x256 uint4
        #pragma unroll
        for (int it = 0; it < 2; it++) {
            int f = tid + it * 256;
            int arr = f >> 8, g = f & 255;
            int row = g >> 3, u = g & 7;
            const __half* src = (arr ? g_vl : g_vh) + vbase + (size_t)(k0 + row) * ND + u * 16;
            cp_async16(base + (arr ? PV_VLO : PV_VHI) + (uint32_t)(row * VSTRIDE + u * 16) * 2, src);
            cp_async16(base + (arr ? PV_VLO : PV_VHI) + (uint32_t)(row * VSTRIDE + u * 16 + 8) * 2, src + 8);
        }
        CP_COMMIT();
    };

    issue_stage(0, 0);

    for (int kc = 0; kc < 32; kc++) {
        if (kc < 31) { issue_stage(kc + 1, (kc + 1) & 1); CP_WAIT(1); }
        else         { CP_WAIT(0); }
        __syncthreads();

        const uint32_t base = uS + (kc & 1) * PV_STAGE;
        #pragma unroll
        for (int ks = 0; ks < 2; ks++) {
            uint32_t ph[2][4], pl[2][4];
            #pragma unroll
            for (int mi = 0; mi < 2; mi++) {
                uint32_t off = ((warpM + mi * 16 + a_row) * TSTRIDE + ks * 16 + a_koff) * 2;
                ldsm_x4(ph[mi], base + PV_PHI + off);
                ldsm_x4(pl[mi], base + PV_PLO + off);
            }
            #pragma unroll
            for (int njp = 0; njp < 2; njp++) {
                uint32_t toff = ((ks * 16 + t_krow) * VSTRIDE + warpN + njp * 16 + t_ncol) * 2;
                uint32_t vh[4], vl[4];
                ldsm_x4_t(vh, base + PV_VHI + toff);
                ldsm_x4_t(vl, base + PV_VLO + toff);
                #pragma unroll
                for (int h = 0; h < 2; h++)
                    #pragma unroll
                    for (int mi = 0; mi < 2; mi++)
                        mma_f32(acc[mi][njp * 2 + h], ph[mi], &vh[h * 2]);
                #pragma unroll
                for (int h = 0; h < 2; h++)
                    #pragma unroll
                    for (int mi = 0; mi < 2; mi++)
                        mma_f16(corr[mi][njp * 2 + h], ph[mi], &vl[h * 2]);
                #pragma unroll
                for (int h = 0; h < 2; h++)
                    #pragma unroll
                    for (int mi = 0; mi < 2; mi++)
                        mma_f16(corr[mi][njp * 2 + h], pl[mi], &vh[h * 2]);
            }
        }
        __syncthreads();
    }

    #pragma unroll
    for (int mi = 0; mi < 2; mi++) {
        #pragma unroll
        for (int nj = 0; nj < 4; nj++) {
            add_corr(acc[mi][nj], corr[mi][nj]);
            int r0 = m0 + warpM + mi * 16 + (lid >> 2);
            int c0 = warpN + nj * 8 + (lid & 3) * 2;
            *(float2*)&o_out[((size_t)(b * NS) + r0) * ND + c0] =
                make_float2(acc[mi][nj][0], acc[mi][nj][1]);
            *(float2*)&o_out[((size_t)(b * NS) + r0 + 8) * ND + c0] =
                make_float2(acc[mi][nj][2], acc[mi][nj][3]);
        }
    }
}

// ---------------------------------------------------------------------------
extern "C" void kernel_launch(void* const* d_in, const int* in_sizes, int n_in,
                              void* d_out, int out_size)
{
    const float* X  = (const float*)d_in[0];
    const float* Wq = (const float*)d_in[1];
    const float* bq = (const float*)d_in[2];
    const float* Wk = (const float*)d_in[3];
    const float* bk = (const float*)d_in[4];
    const float* Wv = (const float*)d_in[5];
    const float* bv = (const float*)d_in[6];

    float* out   = (float*)d_out;                 // [32,1024,128]
    float* probs = out + (size_t)NB * NS * ND;    // [32,1024,1024]

    cudaFuncSetAttribute(qkv_mma_kernel, cudaFuncAttributeMaxDynamicSharedMemorySize, QK_SMEM);
    cudaFuncSetAttribute(score_kernel, cudaFuncAttributeMaxDynamicSharedMemorySize, QK_SMEM);
    cudaFuncSetAttribute(pv_kernel, cudaFuncAttributeMaxDynamicSharedMemorySize, PV_SMEM);

    convx_kernel<<<8192, 256>>>(X);
    convw_kernel<<<48, 256>>>(Wq, Wk, Wv);
    qkv_mma_kernel<<<dim3(256, 3), 512, QK_SMEM>>>(bq, bk, bv);
    score_kernel<<<dim3(8, 8, 32), 512, QK_SMEM>>>(probs);
    softmax_kernel<<<4096, 256>>>(probs);
    pv_kernel<<<dim3(16, 32), 256, PV_SMEM>>>(out);
}

// round 9
// speedup vs baseline: 1.2058x; 1.2058x over previous
#include <cuda_runtime.h>
#include <cuda_bf16.h>
#include <cstdint>
#include <math.h>

#define NB 32
#define NS 1024
#define NH 1024
#define ND 128

// persistent scratch (__device__ globals per allocation rules) — split bf16
__device__ __nv_bfloat16 g_xh[NB * NS * NH];
__device__ __nv_bfloat16 g_xl[NB * NS * NH];
__device__ __nv_bfloat16 g_qh[NB * NS * ND];
__device__ __nv_bfloat16 g_ql[NB * NS * ND];
__device__ __nv_bfloat16 g_kh[NB * NS * ND];
__device__ __nv_bfloat16 g_kl[NB * NS * ND];
__device__ __nv_bfloat16 g_vh[NB * NS * ND];
__device__ __nv_bfloat16 g_vl[NB * NS * ND];
__device__ __nv_bfloat16 g_wthi[3 * ND * NH];  // [w][n][k]
__device__ __nv_bfloat16 g_wtlo[3 * ND * NH];

// ---------------------------------------------------------------------------
// helpers
// ---------------------------------------------------------------------------
__device__ __forceinline__ uint32_t smem_u32(const void* p) {
    uint32_t a;
    asm("{ .reg .u64 t; cvta.to.shared.u64 t, %1; cvt.u32.u64 %0, t; }" : "=r"(a) : "l"(p));
    return a;
}
__device__ __forceinline__ void ldsm_x4(uint32_t* r, uint32_t addr) {
    asm volatile("ldmatrix.sync.aligned.m8n8.x4.shared.b16 {%0,%1,%2,%3}, [%4];"
                 : "=r"(r[0]), "=r"(r[1]), "=r"(r[2]), "=r"(r[3]) : "r"(addr));
}
__device__ __forceinline__ void ldsm_x4_t(uint32_t* r, uint32_t addr) {
    asm volatile("ldmatrix.sync.aligned.m8n8.x4.trans.shared.b16 {%0,%1,%2,%3}, [%4];"
                 : "=r"(r[0]), "=r"(r[1]), "=r"(r[2]), "=r"(r[3]) : "r"(addr));
}
__device__ __forceinline__ void mma16816(float* d, const uint32_t* a, const uint32_t* b) {
    asm volatile(
        "mma.sync.aligned.m16n8k16.row.col.f32.bf16.bf16.f32 "
        "{%0,%1,%2,%3}, {%4,%5,%6,%7}, {%8,%9}, {%0,%1,%2,%3};"
        : "+f"(d[0]), "+f"(d[1]), "+f"(d[2]), "+f"(d[3])
        : "r"(a[0]), "r"(a[1]), "r"(a[2]), "r"(a[3]), "r"(b[0]), "r"(b[1]));
}
__device__ __forceinline__ void split2(float a, float b, uint32_t& hi, uint32_t& lo) {
    __nv_bfloat16 ha = __float2bfloat16(a), hb = __float2bfloat16(b);
    __nv_bfloat16 la = __float2bfloat16(a - __bfloat162float(ha));
    __nv_bfloat16 lb = __float2bfloat16(b - __bfloat162float(hb));
    hi = (uint32_t)__bfloat16_as_ushort(ha) | ((uint32_t)__bfloat16_as_ushort(hb) << 16);
    lo = (uint32_t)__bfloat16_as_ushort(la) | ((uint32_t)__bfloat16_as_ushort(lb) << 16);
}
__device__ __forceinline__ float fast_exp(float x) {
    float t = x * 1.4426950408889634f;
    int ii = __float2int_rn(t);
    float f = t - (float)ii;
    float y = f * 0.6931471805599453f;
    float p = 1.0f + y * (1.0f + y * (0.5f + y * (0.16666667f + y * (0.041666668f + y * 0.008333334f))));
    return __int_as_float(__float_as_int(p) + (ii << 23));
}
__device__ __forceinline__ void cp_async16(uint32_t smem_addr, const void* gptr) {
    asm volatile("cp.async.cg.shared.global [%0], [%1], 16;" :: "r"(smem_addr), "l"(gptr));
}
#define CP_COMMIT() asm volatile("cp.async.commit_group;" ::: "memory")
#define CP_WAIT(n)  asm volatile("cp.async.wait_group %0;" :: "n"(n) : "memory")

// ---------------------------------------------------------------------------
// X split
// ---------------------------------------------------------------------------
__global__ __launch_bounds__(256) void convx_kernel(const float* __restrict__ X)
{
    const int total = NB * NS * NH / 4;
    for (int i = blockIdx.x * 256 + threadIdx.x; i < total; i += gridDim.x * 256) {
        float4 v = ((const float4*)X)[i];
        uint2 h, l;
        split2(v.x, v.y, h.x, l.x);
        split2(v.z, v.w, h.y, l.y);
        ((uint2*)g_xh)[i] = h;
        ((uint2*)g_xl)[i] = l;
    }
}

// ---------------------------------------------------------------------------
// Weight transpose+split
// ---------------------------------------------------------------------------
__global__ __launch_bounds__(256) void convw_kernel(
    const float* __restrict__ Wq, const float* __restrict__ Wk, const float* __restrict__ Wv)
{
    __shared__ float sW[64 * 129];
    int w = blockIdx.x >> 4;
    int k0 = (blockIdx.x & 15) * 64;
    const float* W = (w == 0) ? Wq : (w == 1) ? Wk : Wv;
    int tid = threadIdx.x;

    #pragma unroll
    for (int it = 0; it < 32; it++) {
        int f = tid + it * 256;
        int kk = f >> 7, n = f & 127;
        sW[kk * 129 + n] = W[(size_t)(k0 + kk) * ND + n];
    }
    __syncthreads();

    #pragma unroll
    for (int it = 0; it < 32; it++) {
        int f = tid + it * 256;
        int n = f >> 6, kk = f & 63;
        float x = sW[kk * 129 + n];
        __nv_bfloat16 hi = __float2bfloat16(x);
        __nv_bfloat16 lo = __float2bfloat16(x - __bfloat162float(hi));
        size_t di = (size_t)w * ND * NH + (size_t)n * NH + k0 + kk;
        g_wthi[di] = hi;
        g_wtlo[di] = lo;
    }
}

// ---------------------------------------------------------------------------
// QKV GEMM: 2-stage cp.async, BM=128 BN=128 BK=32, 2 CTAs/SM.
// grid(3, 256): w fastest -> the 3 CTAs sharing an X m-tile co-run (L2 reuse).
// ---------------------------------------------------------------------------
#define TSTRIDE 40
#define QK_AHI 0
#define QK_ALO 10240
#define QK_BHI 20480
#define QK_BLO 30720
#define QK_STAGE 40960
#define QK_SMEM (2 * QK_STAGE)

__global__ __launch_bounds__(256, 2) void qkv_mma_kernel(
    const float* __restrict__ bq, const float* __restrict__ bk, const float* __restrict__ bv)
{
    extern __shared__ char sm[];
    const uint32_t uS = smem_u32(sm);

    const int tid = threadIdx.x;
    const int wid = tid >> 5, lid = tid & 31;
    const int w  = blockIdx.x;            // weight index (fast dim for L2 reuse)
    const int m0 = blockIdx.y * 128;

    const __nv_bfloat16* Whi = g_wthi + (size_t)w * ND * NH;
    const __nv_bfloat16* Wlo = g_wtlo + (size_t)w * ND * NH;
    const float* bias = (w == 0) ? bq : (w == 1) ? bk : bv;
    __nv_bfloat16* outh = (w == 0) ? g_qh : (w == 1) ? g_kh : g_vh;
    __nv_bfloat16* outl = (w == 0) ? g_ql : (w == 1) ? g_kl : g_vl;
    const float oscale = (w == 0) ? 0.08838834764831845f : 1.0f;

    const int warpM = (wid >> 1) * 32;
    const int warpN = (wid & 1) * 64;

    const int a_row  = lid & 15;
    const int a_koff = (lid >> 4) * 8;
    const int bx_row  = (lid & 7) + (lid >> 4) * 8;
    const int bx_koff = ((lid >> 3) & 1) * 8;

    float acc[2][8][4];
    #pragma unroll
    for (int i = 0; i < 2; i++)
        #pragma unroll
        for (int j = 0; j < 8; j++)
            #pragma unroll
            for (int c = 0; c < 4; c++) acc[i][j][c] = 0.f;

    auto issue_stage = [&](int kc, int s) {
        const int k0 = kc * 32;
        const uint32_t base = uS + s * QK_STAGE;
        #pragma unroll
        for (int it = 0; it < 4; it++) {
            int f = tid + it * 256;
            int arr = f >> 9, g = f & 511;
            int row = g >> 2, u = g & 3;
            const __nv_bfloat16* src = (arr ? g_xl : g_xh) + (size_t)(m0 + row) * NH + k0 + u * 8;
            cp_async16(base + (arr ? QK_ALO : QK_AHI) + (uint32_t)(row * TSTRIDE + u * 8) * 2, src);
        }
        #pragma unroll
        for (int it = 0; it < 4; it++) {
            int f = tid + it * 256;
            int arr = f >> 9, g = f & 511;
            int row = g >> 2, u = g & 3;
            const __nv_bfloat16* src = (arr ? Wlo : Whi) + (size_t)row * NH + k0 + u * 8;
            cp_async16(base + (arr ? QK_BLO : QK_BHI) + (uint32_t)(row * TSTRIDE + u * 8) * 2, src);
        }
        CP_COMMIT();
    };

    issue_stage(0, 0);

    for (int kc = 0; kc < 32; kc++) {
        if (kc < 31) { issue_stage(kc + 1, (kc + 1) & 1); CP_WAIT(1); }
        else         { CP_WAIT(0); }
        __syncthreads();

        const uint32_t base = uS + (kc & 1) * QK_STAGE;
        #pragma unroll
        for (int ks = 0; ks < 2; ks++) {
            uint32_t ahi[2][4], alo[2][4];
            #pragma unroll
            for (int mi = 0; mi < 2; mi++) {
                uint32_t off = ((warpM + mi * 16 + a_row) * TSTRIDE + ks * 16 + a_koff) * 2;
                ldsm_x4(ahi[mi], base + QK_AHI + off);
                ldsm_x4(alo[mi], base + QK_ALO + off);
            }
            #pragma unroll
            for (int njp = 0; njp < 4; njp++) {
                uint32_t boff = ((warpN + njp * 16 + bx_row) * TSTRIDE + ks * 16 + bx_koff) * 2;
                uint32_t bh[4], bl[4];
                ldsm_x4(bh, base + QK_BHI + boff);
                ldsm_x4(bl, base + QK_BLO + boff);
                #pragma unroll
                for (int h = 0; h < 2; h++)
                    #pragma unroll
                    for (int mi = 0; mi < 2; mi++)
                        mma16816(acc[mi][njp * 2 + h], ahi[mi], &bh[h * 2]);
                #pragma unroll
                for (int h = 0; h < 2; h++)
                    #pragma unroll
                    for (int mi = 0; mi < 2; mi++)
                        mma16816(acc[mi][njp * 2 + h], ahi[mi], &bl[h * 2]);
                #pragma unroll
                for (int h = 0; h < 2; h++)
                    #pragma unroll
                    for (int mi = 0; mi < 2; mi++)
                        mma16816(acc[mi][njp * 2 + h], alo[mi], &bh[h * 2]);
            }
        }
        __syncthreads();
    }

    #pragma unroll
    for (int mi = 0; mi < 2; mi++) {
        #pragma unroll
        for (int nj = 0; nj < 8; nj++) {
            int r0 = m0 + warpM + mi * 16 + (lid >> 2);
            int c0 = warpN + nj * 8 + (lid & 3) * 2;
            float b0 = bias[c0], b1 = bias[c0 + 1];
            float v0 = (acc[mi][nj][0] + b0) * oscale;
            float v1 = (acc[mi][nj][1] + b1) * oscale;
            float v2 = (acc[mi][nj][2] + b0) * oscale;
            float v3 = (acc[mi][nj][3] + b1) * oscale;
            uint32_t h01, l01, h23, l23;
            split2(v0, v1, h01, l01);
            split2(v2, v3, h23, l23);
            *(uint32_t*)&outh[(size_t)r0 * ND + c0] = h01;
            *(uint32_t*)&outl[(size_t)r0 * ND + c0] = l01;
            *(uint32_t*)&outh[(size_t)(r0 + 8) * ND + c0] = h23;
            *(uint32_t*)&outl[(size_t)(r0 + 8) * ND + c0] = l23;
        }
    }
}

// ---------------------------------------------------------------------------
// score_kernel: raw S = q_scaled @ k^T -> probs buffer (fp32).
// ---------------------------------------------------------------------------
__global__ __launch_bounds__(256, 2) void score_kernel(float* __restrict__ probs)
{
    extern __shared__ char sm[];
    const uint32_t uS = smem_u32(sm);

    const int tid = threadIdx.x;
    const int wid = tid >> 5, lid = tid & 31;
    const int m0 = blockIdx.x * 128;
    const int n0 = blockIdx.y * 128;
    const int b  = blockIdx.z;
    const size_t qbase = (size_t)(b * NS + m0) * ND;
    const size_t kbase = (size_t)(b * NS + n0) * ND;

    const int warpM = (wid >> 1) * 32;
    const int warpN = (wid & 1) * 64;
    const int a_row  = lid & 15;
    const int a_koff = (lid >> 4) * 8;
    const int bx_row  = (lid & 7) + (lid >> 4) * 8;
    const int bx_koff = ((lid >> 3) & 1) * 8;

    float acc[2][8][4];
    #pragma unroll
    for (int i = 0; i < 2; i++)
        #pragma unroll
        for (int j = 0; j < 8; j++)
            #pragma unroll
            for (int c = 0; c < 4; c++) acc[i][j][c] = 0.f;

    auto issue_stage = [&](int kc, int s) {
        const int k0 = kc * 32;
        const uint32_t base = uS + s * QK_STAGE;
        #pragma unroll
        for (int it = 0; it < 4; it++) {
            int f = tid + it * 256;
            int arr = f >> 9, g = f & 511;
            int row = g >> 2, u = g & 3;
            const __nv_bfloat16* src = (arr ? g_ql : g_qh) + qbase + (size_t)row * ND + k0 + u * 8;
            cp_async16(base + (arr ? QK_ALO : QK_AHI) + (uint32_t)(row * TSTRIDE + u * 8) * 2, src);
        }
        #pragma unroll
        for (int it = 0; it < 4; it++) {
            int f = tid + it * 256;
            int arr = f >> 9, g = f & 511;
            int row = g >> 2, u = g & 3;
            const __nv_bfloat16* src = (arr ? g_kl : g_kh) + kbase + (size_t)row * ND + k0 + u * 8;
            cp_async16(base + (arr ? QK_BLO : QK_BHI) + (uint32_t)(row * TSTRIDE + u * 8) * 2, src);
        }
        CP_COMMIT();
    };

    issue_stage(0, 0);

    for (int kc = 0; kc < 4; kc++) {
        if (kc < 3) { issue_stage(kc + 1, (kc + 1) & 1); CP_WAIT(1); }
        else        { CP_WAIT(0); }
        __syncthreads();

        const uint32_t base = uS + (kc & 1) * QK_STAGE;
        #pragma unroll
        for (int ks = 0; ks < 2; ks++) {
            uint32_t ahi[2][4], alo[2][4];
            #pragma unroll
            for (int mi = 0; mi < 2; mi++) {
                uint32_t off = ((warpM + mi * 16 + a_row) * TSTRIDE + ks * 16 + a_koff) * 2;
                ldsm_x4(ahi[mi], base + QK_AHI + off);
                ldsm_x4(alo[mi], base + QK_ALO + off);
            }
            #pragma unroll
            for (int njp = 0; njp < 4; njp++) {
                uint32_t boff = ((warpN + njp * 16 + bx_row) * TSTRIDE + ks * 16 + bx_koff) * 2;
                uint32_t bh[4], bl[4];
                ldsm_x4(bh, base + QK_BHI + boff);
                ldsm_x4(bl, base + QK_BLO + boff);
                #pragma unroll
                for (int h = 0; h < 2; h++)
                    #pragma unroll
                    for (int mi = 0; mi < 2; mi++)
                        mma16816(acc[mi][njp * 2 + h], ahi[mi], &bh[h * 2]);
                #pragma unroll
                for (int h = 0; h < 2; h++)
                    #pragma unroll
                    for (int mi = 0; mi < 2; mi++)
                        mma16816(acc[mi][njp * 2 + h], ahi[mi], &bl[h * 2]);
                #pragma unroll
                for (int h = 0; h < 2; h++)
                    #pragma unroll
                    for (int mi = 0; mi < 2; mi++)
                        mma16816(acc[mi][njp * 2 + h], alo[mi], &bh[h * 2]);
            }
        }
        __syncthreads();
    }

    float* pb = probs + (size_t)b * NS * NS;
    #pragma unroll
    for (int mi = 0; mi < 2; mi++) {
        #pragma unroll
        for (int nj = 0; nj < 8; nj++) {
            int r0 = m0 + warpM + mi * 16 + (lid >> 2);
            int c0 = n0 + warpN + nj * 8 + (lid & 3) * 2;
            *(float2*)&pb[(size_t)r0 * NS + c0]       = make_float2(acc[mi][nj][0], acc[mi][nj][1]);
            *(float2*)&pb[(size_t)(r0 + 8) * NS + c0] = make_float2(acc[mi][nj][2], acc[mi][nj][3]);
        }
    }
}

// ---------------------------------------------------------------------------
// softmax_kernel: warp per row, register resident; normalizes probs in place.
// (no split-P side outputs — pv reads fp32 probs directly)
// ---------------------------------------------------------------------------
__global__ __launch_bounds__(256) void softmax_kernel(float* __restrict__ probs)
{
    const int wid = threadIdx.x >> 5, lid = threadIdx.x & 31;
    const int row = blockIdx.x * 8 + wid;
    const size_t base4 = (size_t)row * (NS / 4);

    float4 v[8];
    #pragma unroll
    for (int u = 0; u < 8; u++) v[u] = ((const float4*)probs)[base4 + lid + u * 32];

    float mx = -1e30f;
    #pragma unroll
    for (int u = 0; u < 8; u++) {
        mx = fmaxf(mx, fmaxf(fmaxf(v[u].x, v[u].y), fmaxf(v[u].z, v[u].w)));
    }
    #pragma unroll
    for (int o = 1; o < 32; o <<= 1) mx = fmaxf(mx, __shfl_xor_sync(0xffffffffu, mx, o));

    float sum = 0.f;
    #pragma unroll
    for (int u = 0; u < 8; u++) {
        v[u].x = fast_exp(v[u].x - mx);
        v[u].y = fast_exp(v[u].y - mx);
        v[u].z = fast_exp(v[u].z - mx);
        v[u].w = fast_exp(v[u].w - mx);
        sum += (v[u].x + v[u].y) + (v[u].z + v[u].w);
    }
    #pragma unroll
    for (int o = 1; o < 32; o <<= 1) sum += __shfl_xor_sync(0xffffffffu, sum, o);
    const float inv = 1.f / sum;

    #pragma unroll
    for (int u = 0; u < 8; u++) {
        v[u].x *= inv; v[u].y *= inv; v[u].z *= inv; v[u].w *= inv;
        ((float4*)probs)[base4 + lid + u * 32] = v[u];
    }
}

// ---------------------------------------------------------------------------
// pv_kernel: O = P @ V. grid(8,32), BM=128, K=1024, BK=32, 2 CTAs/SM.
// P staged as fp32 (stride 44 floats, conflict-free), split to bf16 inline.
// V staged split bf16, trans-ldsm.
// ---------------------------------------------------------------------------
#define PSTRIDE 44
#define PV_P   0
#define PV_PB  22528                      // 128*44*4
#define PV_VHI 22528
#define PV_VLO 31232                      // +32*136*2
#define PV_STAGE 39936
#define PV_SMEM (2 * PV_STAGE)
#define VSTRIDE 136

__global__ __launch_bounds__(256, 2) void pv_kernel(const float* __restrict__ probs,
                                                    float* __restrict__ o_out)
{
    extern __shared__ char sm[];
    const uint32_t uS = smem_u32(sm);

    const int tid = threadIdx.x;
    const int wid = tid >> 5, lid = tid & 31;
    const int m0 = blockIdx.x * 128;
    const int b  = blockIdx.y;
    const size_t pbase = (size_t)(b * NS + m0) * NS;
    const size_t vbase = (size_t)(b * NS) * ND;

    const int warpM = (wid >> 1) * 32;
    const int warpN = (wid & 1) * 64;
    const int t_krow = (lid & 7) + ((lid >> 3) & 1) * 8;
    const int t_ncol = (lid >> 4) * 8;
    const int p_row  = lid >> 2;          // 0..7
    const int p_col  = (lid & 3) * 2;     // 0,2,4,6

    float acc[2][8][4];
    #pragma unroll
    for (int i = 0; i < 2; i++)
        #pragma unroll
        for (int j = 0; j < 8; j++)
            #pragma unroll
            for (int c = 0; c < 4; c++) acc[i][j][c] = 0.f;

    auto issue_stage = [&](int kc, int s) {
        const int k0 = kc * 32;
        const uint32_t base = uS + s * PV_STAGE;
        // P tile: 128 q-rows x 32 k fp32 = 1024 cp16
        #pragma unroll
        for (int it = 0; it < 4; it++) {
            int f = tid + it * 256;
            int row = f >> 3, u = f & 7;
            const float* src = probs + pbase + (size_t)row * NS + k0 + u * 4;
            cp_async16(base + PV_P + (uint32_t)(row * PSTRIDE + u * 4) * 4, src);
        }
        // V tile: 32 k-rows x 128 d split bf16 = 1024 cp16
        #pragma unroll
        for (int it = 0; it < 4; it++) {
            int f = tid + it * 256;
            int arr = f >> 9, g = f & 511;
            int row = g >> 4, u = g & 15;
            const __nv_bfloat16* src = (arr ? g_vl : g_vh) + vbase + (size_t)(k0 + row) * ND + u * 8;
            cp_async16(base + (arr ? PV_VLO : PV_VHI) + (uint32_t)(row * VSTRIDE + u * 8) * 2, src);
        }
        CP_COMMIT();
    };

    issue_stage(0, 0);

    for (int kc = 0; kc < 32; kc++) {
        if (kc < 31) { issue_stage(kc + 1, (kc + 1) & 1); CP_WAIT(1); }
        else         { CP_WAIT(0); }
        __syncthreads();

        const char* stg = sm + (kc & 1) * PV_STAGE;
        const float* Pb = (const float*)(stg + PV_P);
        const uint32_t vb = uS + (kc & 1) * PV_STAGE;

        #pragma unroll
        for (int ks = 0; ks < 2; ks++) {
            // build P fragments from fp32 smem (inline split)
            uint32_t ph[2][4], pl[2][4];
            #pragma unroll
            for (int mi = 0; mi < 2; mi++) {
                int row  = warpM + mi * 16 + p_row;
                int kcol = ks * 16 + p_col;
                float2 p0 = *(const float2*)&Pb[row * PSTRIDE + kcol];
                float2 p1 = *(const float2*)&Pb[(row + 8) * PSTRIDE + kcol];
                float2 p2 = *(const float2*)&Pb[row * PSTRIDE + kcol + 8];
                float2 p3 = *(const float2*)&Pb[(row + 8) * PSTRIDE + kcol + 8];
                split2(p0.x, p0.y, ph[mi][0], pl[mi][0]);
                split2(p1.x, p1.y, ph[mi][1], pl[mi][1]);
                split2(p2.x, p2.y, ph[mi][2], pl[mi][2]);
                split2(p3.x, p3.y, ph[mi][3], pl[mi][3]);
            }
            #pragma unroll
            for (int njp = 0; njp < 4; njp++) {
                uint32_t toff = (uint32_t)((ks * 16 + t_krow) * VSTRIDE + warpN + njp * 16 + t_ncol) * 2;
                uint32_t vh[4], vl[4];
                ldsm_x4_t(vh, vb + PV_VHI + toff);
                ldsm_x4_t(vl, vb + PV_VLO + toff);
                #pragma unroll
                for (int h = 0; h < 2; h++)
                    #pragma unroll
                    for (int mi = 0; mi < 2; mi++)
                        mma16816(acc[mi][njp * 2 + h], ph[mi], &vh[h * 2]);
                #pragma unroll
                for (int h = 0; h < 2; h++)
                    #pragma unroll
                    for (int mi = 0; mi < 2; mi++)
                        mma16816(acc[mi][njp * 2 + h], ph[mi], &vl[h * 2]);
                #pragma unroll
                for (int h = 0; h < 2; h++)
                    #pragma unroll
                    for (int mi = 0; mi < 2; mi++)
                        mma16816(acc[mi][njp * 2 + h], pl[mi], &vh[h * 2]);
            }
        }
        __syncthreads();
    }

    #pragma unroll
    for (int mi = 0; mi < 2; mi++) {
        #pragma unroll
        for (int nj = 0; nj < 8; nj++) {
            int r0 = m0 + warpM + mi * 16 + (lid >> 2);
            int c0 = warpN + nj * 8 + (lid & 3) * 2;
            *(float2*)&o_out[((size_t)(b * NS) + r0) * ND + c0] =
                make_float2(acc[mi][nj][0], acc[mi][nj][1]);
            *(float2*)&o_out[((size_t)(b * NS) + r0 + 8) * ND + c0] =
                make_float2(acc[mi][nj][2], acc[mi][nj][3]);
        }
    }
}

// ---------------------------------------------------------------------------
extern "C" void kernel_launch(void* const* d_in, const int* in_sizes, int n_in,
                              void* d_out, int out_size)
{
    const float* X  = (const float*)d_in[0];
    const float* Wq = (const float*)d_in[1];
    const float* bq = (const float*)d_in[2];
    const float* Wk = (const float*)d_in[3];
    const float* bk = (const float*)d_in[4];
    const float* Wv = (const float*)d_in[5];
    const float* bv = (const float*)d_in[6];

    float* out   = (float*)d_out;                 // [32,1024,128]
    float* probs = out + (size_t)NB * NS * ND;    // [32,1024,1024]

    cudaFuncSetAttribute(qkv_mma_kernel, cudaFuncAttributeMaxDynamicSharedMemorySize, QK_SMEM);
    cudaFuncSetAttribute(score_kernel, cudaFuncAttributeMaxDynamicSharedMemorySize, QK_SMEM);
    cudaFuncSetAttribute(pv_kernel, cudaFuncAttributeMaxDynamicSharedMemorySize, PV_SMEM);

    convx_kernel<<<8192, 256>>>(X);
    convw_kernel<<<48, 256>>>(Wq, Wk, Wv);
    qkv_mma_kernel<<<dim3(3, 256), 256, QK_SMEM>>>(bq, bk, bv);
    score_kernel<<<dim3(8, 8, 32), 256, QK_SMEM>>>(probs);
    softmax_kernel<<<4096, 256>>>(probs);
    pv_kernel<<<dim3(8, 32), 256, PV_SMEM>>>(probs, out);
}

// round 11
// speedup vs baseline: 1.2713x; 1.0543x over previous
#include <cuda_runtime.h>
#include <cuda_bf16.h>
#include <cstdint>
#include <math.h>

#define NB 32
#define NS 1024
#define NH 1024
#define ND 128

// persistent scratch (__device__ globals per allocation rules) — split bf16
__device__ __nv_bfloat16 g_qh[NB * NS * ND];
__device__ __nv_bfloat16 g_ql[NB * NS * ND];
__device__ __nv_bfloat16 g_kh[NB * NS * ND];
__device__ __nv_bfloat16 g_kl[NB * NS * ND];
__device__ __nv_bfloat16 g_vh[NB * NS * ND];
__device__ __nv_bfloat16 g_vl[NB * NS * ND];
__device__ __nv_bfloat16 g_wthi[3 * ND * NH];  // [w][n][k]
__device__ __nv_bfloat16 g_wtlo[3 * ND * NH];

// ---------------------------------------------------------------------------
// helpers
// ---------------------------------------------------------------------------
__device__ __forceinline__ uint32_t smem_u32(const void* p) {
    uint32_t a;
    asm("{ .reg .u64 t; cvta.to.shared.u64 t, %1; cvt.u32.u64 %0, t; }" : "=r"(a) : "l"(p));
    return a;
}
__device__ __forceinline__ void ldsm_x4(uint32_t* r, uint32_t addr) {
    asm volatile("ldmatrix.sync.aligned.m8n8.x4.shared.b16 {%0,%1,%2,%3}, [%4];"
                 : "=r"(r[0]), "=r"(r[1]), "=r"(r[2]), "=r"(r[3]) : "r"(addr));
}
__device__ __forceinline__ void ldsm_x4_t(uint32_t* r, uint32_t addr) {
    asm volatile("ldmatrix.sync.aligned.m8n8.x4.trans.shared.b16 {%0,%1,%2,%3}, [%4];"
                 : "=r"(r[0]), "=r"(r[1]), "=r"(r[2]), "=r"(r[3]) : "r"(addr));
}
__device__ __forceinline__ void mma16816(float* d, const uint32_t* a, const uint32_t* b) {
    asm volatile(
        "mma.sync.aligned.m16n8k16.row.col.f32.bf16.bf16.f32 "
        "{%0,%1,%2,%3}, {%4,%5,%6,%7}, {%8,%9}, {%0,%1,%2,%3};"
        : "+f"(d[0]), "+f"(d[1]), "+f"(d[2]), "+f"(d[3])
        : "r"(a[0]), "r"(a[1]), "r"(a[2]), "r"(a[3]), "r"(b[0]), "r"(b[1]));
}
__device__ __forceinline__ void split2(float a, float b, uint32_t& hi, uint32_t& lo) {
    __nv_bfloat16 ha = __float2bfloat16(a), hb = __float2bfloat16(b);
    __nv_bfloat16 la = __float2bfloat16(a - __bfloat162float(ha));
    __nv_bfloat16 lb = __float2bfloat16(b - __bfloat162float(hb));
    hi = (uint32_t)__bfloat16_as_ushort(ha) | ((uint32_t)__bfloat16_as_ushort(hb) << 16);
    lo = (uint32_t)__bfloat16_as_ushort(la) | ((uint32_t)__bfloat16_as_ushort(lb) << 16);
}
__device__ __forceinline__ float fast_exp(float x) {
    float t = x * 1.4426950408889634f;
    int ii = __float2int_rn(t);
    float f = t - (float)ii;
    float y = f * 0.6931471805599453f;
    float p = 1.0f + y * (1.0f + y * (0.5f + y * (0.16666667f + y * (0.041666668f + y * 0.008333334f))));
    return __int_as_float(__float_as_int(p) + (ii << 23));
}
__device__ __forceinline__ void cp_async16(uint32_t smem_addr, const void* gptr) {
    asm volatile("cp.async.cg.shared.global [%0], [%1], 16;" :: "r"(smem_addr), "l"(gptr));
}
#define CP_COMMIT() asm volatile("cp.async.commit_group;" ::: "memory")
#define CP_WAIT(n)  asm volatile("cp.async.wait_group %0;" :: "n"(n) : "memory")

// ---------------------------------------------------------------------------
// Weight transpose+split
// ---------------------------------------------------------------------------
__global__ __launch_bounds__(256) void convw_kernel(
    const float* __restrict__ Wq, const float* __restrict__ Wk, const float* __restrict__ Wv)
{
    __shared__ float sW[64 * 129];
    int w = blockIdx.x >> 4;
    int k0 = (blockIdx.x & 15) * 64;
    const float* W = (w == 0) ? Wq : (w == 1) ? Wk : Wv;
    int tid = threadIdx.x;

    #pragma unroll
    for (int it = 0; it < 32; it++) {
        int f = tid + it * 256;
        int kk = f >> 7, n = f & 127;
        sW[kk * 129 + n] = W[(size_t)(k0 + kk) * ND + n];
    }
    __syncthreads();

    #pragma unroll
    for (int it = 0; it < 32; it++) {
        int f = tid + it * 256;
        int n = f >> 6, kk = f & 63;
        float x = sW[kk * 129 + n];
        __nv_bfloat16 hi = __float2bfloat16(x);
        __nv_bfloat16 lo = __float2bfloat16(x - __bfloat162float(hi));
        size_t di = (size_t)w * ND * NH + (size_t)n * NH + k0 + kk;
        g_wthi[di] = hi;
        g_wtlo[di] = lo;
    }
}

// ---------------------------------------------------------------------------
// QKV GEMM: BM=128 BN=128 BK=32, 128 threads (4 warps 2x2, warp 64x64).
// A = X staged fp32 (split to bf16 inline — convx fused); B = split weights.
// grid(3 w-fast, 256 m) so the 3 CTAs sharing an X tile co-run.
// ---------------------------------------------------------------------------
#define FSTRIDE 36                           // fp32 A/P smem stride (floats)
#define BSTRIDE 40                           // bf16 tile stride (elems)
#define QK_A   0                             // 128 x 36 fp32 = 18432 B
#define QK_BHI 18432                         // 128 x 40 bf16 = 10240 B
#define QK_BLO 28672
#define QK_STAGE 38912
#define QK_SMEM (2 * QK_STAGE)

__global__ __launch_bounds__(128, 2) void qkv_mma_kernel(
    const float* __restrict__ X,
    const float* __restrict__ bq, const float* __restrict__ bk, const float* __restrict__ bv)
{
    extern __shared__ char sm[];
    const uint32_t uS = smem_u32(sm);

    const int tid = threadIdx.x;
    const int wid = tid >> 5, lid = tid & 31;
    const int w  = blockIdx.x;
    const int m0 = blockIdx.y * 128;

    const __nv_bfloat16* Whi = g_wthi + (size_t)w * ND * NH;
    const __nv_bfloat16* Wlo = g_wtlo + (size_t)w * ND * NH;
    const float* bias = (w == 0) ? bq : (w == 1) ? bk : bv;
    __nv_bfloat16* outh = (w == 0) ? g_qh : (w == 1) ? g_kh : g_vh;
    __nv_bfloat16* outl = (w == 0) ? g_ql : (w == 1) ? g_kl : g_vl;
    const float oscale = (w == 0) ? 0.08838834764831845f : 1.0f;

    const int warpM = (wid >> 1) * 64;       // 0, 64
    const int warpN = (wid & 1) * 64;        // 0, 64

    const int bx_row  = (lid & 7) + (lid >> 4) * 8;
    const int bx_koff = ((lid >> 3) & 1) * 8;
    const int p_row = lid >> 2;              // 0..7
    const int p_col = (lid & 3) * 2;         // 0,2,4,6

    float acc[4][8][4];
    #pragma unroll
    for (int i = 0; i < 4; i++)
        #pragma unroll
        for (int j = 0; j < 8; j++)
            #pragma unroll
            for (int c = 0; c < 4; c++) acc[i][j][c] = 0.f;

    auto issue_stage = [&](int kc, int s) {
        const int k0 = kc * 32;
        const uint32_t base = uS + s * QK_STAGE;
        // A: 128 rows x 32 fp32 = 1024 cp16 (8 its x 128 thr)
        #pragma unroll
        for (int it = 0; it < 8; it++) {
            int f = tid + it * 128;
            int row = f >> 3, u = f & 7;
            const float* src = X + (size_t)(m0 + row) * NH + k0 + u * 4;
            cp_async16(base + QK_A + (uint32_t)(row * FSTRIDE + u * 4) * 4, src);
        }
        // B: hi/lo 128 rows x 32 bf16 = 1024 cp16 (8 its x 128 thr)
        #pragma unroll
        for (int it = 0; it < 8; it++) {
            int f = tid + it * 128;
            int arr = f >> 9, g = f & 511;
            int row = g >> 2, u = g & 3;
            const __nv_bfloat16* src = (arr ? Wlo : Whi) + (size_t)row * NH + k0 + u * 8;
            cp_async16(base + (arr ? QK_BLO : QK_BHI) + (uint32_t)(row * BSTRIDE + u * 8) * 2, src);
        }
        CP_COMMIT();
    };

    issue_stage(0, 0);

    for (int kc = 0; kc < 32; kc++) {
        if (kc < 31) { issue_stage(kc + 1, (kc + 1) & 1); CP_WAIT(1); }
        else         { CP_WAIT(0); }
        __syncthreads();

        const float* Ab = (const float*)(sm + (kc & 1) * QK_STAGE + QK_A);
        const uint32_t bb = uS + (kc & 1) * QK_STAGE;

        #pragma unroll
        for (int ks = 0; ks < 2; ks++) {
            uint32_t ah[4][4], al[4][4];
            #pragma unroll
            for (int mi = 0; mi < 4; mi++) {
                int row  = warpM + mi * 16 + p_row;
                int kcol = ks * 16 + p_col;
                float2 p0 = *(const float2*)&Ab[row * FSTRIDE + kcol];
                float2 p1 = *(const float2*)&Ab[(row + 8) * FSTRIDE + kcol];
                float2 p2 = *(const float2*)&Ab[row * FSTRIDE + kcol + 8];
                float2 p3 = *(const float2*)&Ab[(row + 8) * FSTRIDE + kcol + 8];
                split2(p0.x, p0.y, ah[mi][0], al[mi][0]);
                split2(p1.x, p1.y, ah[mi][1], al[mi][1]);
                split2(p2.x, p2.y, ah[mi][2], al[mi][2]);
                split2(p3.x, p3.y, ah[mi][3], al[mi][3]);
            }
            #pragma unroll
            for (int njp = 0; njp < 4; njp++) {
                uint32_t boff = ((warpN + njp * 16 + bx_row) * BSTRIDE + ks * 16 + bx_koff) * 2;
                uint32_t bh[4], bl[4];
                ldsm_x4(bh, bb + QK_BHI + boff);
                ldsm_x4(bl, bb + QK_BLO + boff);
                #pragma unroll
                for (int h = 0; h < 2; h++)
                    #pragma unroll
                    for (int mi = 0; mi < 4; mi++)
                        mma16816(acc[mi][njp * 2 + h], ah[mi], &bh[h * 2]);
                #pragma unroll
                for (int h = 0; h < 2; h++)
                    #pragma unroll
                    for (int mi = 0; mi < 4; mi++)
                        mma16816(acc[mi][njp * 2 + h], ah[mi], &bl[h * 2]);
                #pragma unroll
                for (int h = 0; h < 2; h++)
                    #pragma unroll
                    for (int mi = 0; mi < 4; mi++)
                        mma16816(acc[mi][njp * 2 + h], al[mi], &bh[h * 2]);
            }
        }
        __syncthreads();
    }

    #pragma unroll
    for (int mi = 0; mi < 4; mi++) {
        #pragma unroll
        for (int nj = 0; nj < 8; nj++) {
            int r0 = m0 + warpM + mi * 16 + (lid >> 2);
            int c0 = warpN + nj * 8 + (lid & 3) * 2;
            float b0 = bias[c0], b1 = bias[c0 + 1];
            float v0 = (acc[mi][nj][0] + b0) * oscale;
            float v1 = (acc[mi][nj][1] + b1) * oscale;
            float v2 = (acc[mi][nj][2] + b0) * oscale;
            float v3 = (acc[mi][nj][3] + b1) * oscale;
            uint32_t h01, l01, h23, l23;
            split2(v0, v1, h01, l01);
            split2(v2, v3, h23, l23);
            *(uint32_t*)&outh[(size_t)r0 * ND + c0] = h01;
            *(uint32_t*)&outl[(size_t)r0 * ND + c0] = l01;
            *(uint32_t*)&outh[(size_t)(r0 + 8) * ND + c0] = h23;
            *(uint32_t*)&outl[(size_t)(r0 + 8) * ND + c0] = l23;
        }
    }
}

// ---------------------------------------------------------------------------
// score_kernel: raw S = q_scaled @ k^T -> probs buffer (fp32).
// 128 threads, 4 warps 2x2, warp 64x64.
// ---------------------------------------------------------------------------
#define SC_QH 0
#define SC_QL 10240
#define SC_KH 20480
#define SC_KL 30720
#define SC_STAGE 40960
#define SC_SMEM (2 * SC_STAGE)

__global__ __launch_bounds__(128, 2) void score_kernel(float* __restrict__ probs)
{
    extern __shared__ char sm[];
    const uint32_t uS = smem_u32(sm);

    const int tid = threadIdx.x;
    const int wid = tid >> 5, lid = tid & 31;
    const int m0 = blockIdx.x * 128;
    const int n0 = blockIdx.y * 128;
    const int b  = blockIdx.z;
    const size_t qbase = (size_t)(b * NS + m0) * ND;
    const size_t kbase = (size_t)(b * NS + n0) * ND;

    const int warpM = (wid >> 1) * 64;
    const int warpN = (wid & 1) * 64;
    const int a_row  = lid & 15;
    const int a_koff = (lid >> 4) * 8;
    const int bx_row  = (lid & 7) + (lid >> 4) * 8;
    const int bx_koff = ((lid >> 3) & 1) * 8;

    float acc[4][8][4];
    #pragma unroll
    for (int i = 0; i < 4; i++)
        #pragma unroll
        for (int j = 0; j < 8; j++)
            #pragma unroll
            for (int c = 0; c < 4; c++) acc[i][j][c] = 0.f;

    auto issue_stage = [&](int kc, int s) {
        const int k0 = kc * 32;
        const uint32_t base = uS + s * SC_STAGE;
        // 4 arrays x 128 rows x 32 bf16 = 2048 cp16 (16 its x 128 thr)
        #pragma unroll
        for (int it = 0; it < 16; it++) {
            int f = tid + it * 128;
            int arr = f >> 9;                // 0=Qh,1=Ql,2=Kh,3=Kl
            int g = f & 511;
            int row = g >> 2, u = g & 3;
            const __nv_bfloat16* src;
            uint32_t off;
            if (arr == 0)      { src = g_qh + qbase; off = SC_QH; }
            else if (arr == 1) { src = g_ql + qbase; off = SC_QL; }
            else if (arr == 2) { src = g_kh + kbase; off = SC_KH; }
            else               { src = g_kl + kbase; off = SC_KL; }
            cp_async16(base + off + (uint32_t)(row * BSTRIDE + u * 8) * 2,
                       src + (size_t)row * ND + k0 + u * 8);
        }
        CP_COMMIT();
    };

    issue_stage(0, 0);

    for (int kc = 0; kc < 4; kc++) {
        if (kc < 3) { issue_stage(kc + 1, (kc + 1) & 1); CP_WAIT(1); }
        else        { CP_WAIT(0); }
        __syncthreads();

        const uint32_t base = uS + (kc & 1) * SC_STAGE;
        #pragma unroll
        for (int ks = 0; ks < 2; ks++) {
            uint32_t ahi[4][4], alo[4][4];
            #pragma unroll
            for (int mi = 0; mi < 4; mi++) {
                uint32_t off = ((warpM + mi * 16 + a_row) * BSTRIDE + ks * 16 + a_koff) * 2;
                ldsm_x4(ahi[mi], base + SC_QH + off);
                ldsm_x4(alo[mi], base + SC_QL + off);
            }
            #pragma unroll
            for (int njp = 0; njp < 4; njp++) {
                uint32_t boff = ((warpN + njp * 16 + bx_row) * BSTRIDE + ks * 16 + bx_koff) * 2;
                uint32_t bh[4], bl[4];
                ldsm_x4(bh, base + SC_KH + boff);
                ldsm_x4(bl, base + SC_KL + boff);
                #pragma unroll
                for (int h = 0; h < 2; h++)
                    #pragma unroll
                    for (int mi = 0; mi < 4; mi++)
                        mma16816(acc[mi][njp * 2 + h], ahi[mi], &bh[h * 2]);
                #pragma unroll
                for (int h = 0; h < 2; h++)
                    #pragma unroll
                    for (int mi = 0; mi < 4; mi++)
                        mma16816(acc[mi][njp * 2 + h], ahi[mi], &bl[h * 2]);
                #pragma unroll
                for (int h = 0; h < 2; h++)
                    #pragma unroll
                    for (int mi = 0; mi < 4; mi++)
                        mma16816(acc[mi][njp * 2 + h], alo[mi], &bh[h * 2]);
            }
        }
        __syncthreads();
    }

    float* pb = probs + (size_t)b * NS * NS;
    #pragma unroll
    for (int mi = 0; mi < 4; mi++) {
        #pragma unroll
        for (int nj = 0; nj < 8; nj++) {
            int r0 = m0 + warpM + mi * 16 + (lid >> 2);
            int c0 = n0 + warpN + nj * 8 + (lid & 3) * 2;
            *(float2*)&pb[(size_t)r0 * NS + c0]       = make_float2(acc[mi][nj][0], acc[mi][nj][1]);
            *(float2*)&pb[(size_t)(r0 + 8) * NS + c0] = make_float2(acc[mi][nj][2], acc[mi][nj][3]);
        }
    }
}

// ---------------------------------------------------------------------------
// softmax_kernel: warp per row, register resident; normalizes probs in place.
// ---------------------------------------------------------------------------
__global__ __launch_bounds__(256) void softmax_kernel(float* __restrict__ probs)
{
    const int wid = threadIdx.x >> 5, lid = threadIdx.x & 31;
    const int row = blockIdx.x * 8 + wid;
    const size_t base4 = (size_t)row * (NS / 4);

    float4 v[8];
    #pragma unroll
    for (int u = 0; u < 8; u++) v[u] = ((const float4*)probs)[base4 + lid + u * 32];

    float mx = -1e30f;
    #pragma unroll
    for (int u = 0; u < 8; u++) {
        mx = fmaxf(mx, fmaxf(fmaxf(v[u].x, v[u].y), fmaxf(v[u].z, v[u].w)));
    }
    #pragma unroll
    for (int o = 1; o < 32; o <<= 1) mx = fmaxf(mx, __shfl_xor_sync(0xffffffffu, mx, o));

    float sum = 0.f;
    #pragma unroll
    for (int u = 0; u < 8; u++) {
        v[u].x = fast_exp(v[u].x - mx);
        v[u].y = fast_exp(v[u].y - mx);
        v[u].z = fast_exp(v[u].z - mx);
        v[u].w = fast_exp(v[u].w - mx);
        sum += (v[u].x + v[u].y) + (v[u].z + v[u].w);
    }
    #pragma unroll
    for (int o = 1; o < 32; o <<= 1) sum += __shfl_xor_sync(0xffffffffu, sum, o);
    const float inv = 1.f / sum;

    #pragma unroll
    for (int u = 0; u < 8; u++) {
        v[u].x *= inv; v[u].y *= inv; v[u].z *= inv; v[u].w *= inv;
        ((float4*)probs)[base4 + lid + u * 32] = v[u];
    }
}

// ---------------------------------------------------------------------------
// pv_kernel: O = P @ V. 128 threads, 4 warps 2x2, warp 64x64, K=1024 BK=32.
// P staged fp32 (inline split); V staged split bf16 (trans ldsm).
// ---------------------------------------------------------------------------
#define PV_P   0                             // 128 x 36 fp32 = 18432 B
#define PV_VHI 18432                         // 32 x 136 bf16 = 8704 B
#define PV_VLO 27136
#define PV_STAGE 35840
#define PV_SMEM (2 * PV_STAGE)
#define VSTRIDE 136

__global__ __launch_bounds__(128, 2) void pv_kernel(const float* __restrict__ probs,
                                                    float* __restrict__ o_out)
{
    extern __shared__ char sm[];
    const uint32_t uS = smem_u32(sm);

    const int tid = threadIdx.x;
    const int wid = tid >> 5, lid = tid & 31;
    const int m0 = blockIdx.x * 128;
    const int b  = blockIdx.y;
    const size_t pbase = (size_t)(b * NS + m0) * NS;
    const size_t vbase = (size_t)(b * NS) * ND;

    const int warpM = (wid >> 1) * 64;
    const int warpN = (wid & 1) * 64;
    const int t_krow = (lid & 7) + ((lid >> 3) & 1) * 8;
    const int t_ncol = (lid >> 4) * 8;
    const int p_row = lid >> 2;
    const int p_col = (lid & 3) * 2;

    float acc[4][8][4];
    #pragma unroll
    for (int i = 0; i < 4; i++)
        #pragma unroll
        for (int j = 0; j < 8; j++)
            #pragma unroll
            for (int c = 0; c < 4; c++) acc[i][j][c] = 0.f;

    auto issue_stage = [&](int kc, int s) {
        const int k0 = kc * 32;
        const uint32_t base = uS + s * PV_STAGE;
        // P: 128 rows x 32 fp32 = 1024 cp16 (8 its)
        #pragma unroll
        for (int it = 0; it < 8; it++) {
            int f = tid + it * 128;
            int row = f >> 3, u = f & 7;
            const float* src = probs + pbase + (size_t)row * NS + k0 + u * 4;
            cp_async16(base + PV_P + (uint32_t)(row * FSTRIDE + u * 4) * 4, src);
        }
        // V: hi/lo 32 rows x 128 bf16 = 1024 cp16 (8 its)
        #pragma unroll
        for (int it = 0; it < 8; it++) {
            int f = tid + it * 128;
            int arr = f >> 9, g = f & 511;
            int row = g >> 4, u = g & 15;
            const __nv_bfloat16* src = (arr ? g_vl : g_vh) + vbase + (size_t)(k0 + row) * ND + u * 8;
            cp_async16(base + (arr ? PV_VLO : PV_VHI) + (uint32_t)(row * VSTRIDE + u * 8) * 2, src);
        }
        CP_COMMIT();
    };

    issue_stage(0, 0);

    for (int kc = 0; kc < 32; kc++) {
        if (kc < 31) { issue_stage(kc + 1, (kc + 1) & 1); CP_WAIT(1); }
        else         { CP_WAIT(0); }
        __syncthreads();

        const float* Pb = (const float*)(sm + (kc & 1) * PV_STAGE + PV_P);
        const uint32_t vb = uS + (kc & 1) * PV_STAGE;

        #pragma unroll
        for (int ks = 0; ks < 2; ks++) {
            uint32_t ph[4][4], pl[4][4];
            #pragma unroll
            for (int mi = 0; mi < 4; mi++) {
                int row  = warpM + mi * 16 + p_row;
                int kcol = ks * 16 + p_col;
                float2 p0 = *(const float2*)&Pb[row * FSTRIDE + kcol];
                float2 p1 = *(const float2*)&Pb[(row + 8) * FSTRIDE + kcol];
                float2 p2 = *(const float2*)&Pb[row * FSTRIDE + kcol + 8];
                float2 p3 = *(const float2*)&Pb[(row + 8) * FSTRIDE + kcol + 8];
                split2(p0.x, p0.y, ph[mi][0], pl[mi][0]);
                split2(p1.x, p1.y, ph[mi][1], pl[mi][1]);
                split2(p2.x, p2.y, ph[mi][2], pl[mi][2]);
                split2(p3.x, p3.y, ph[mi][3], pl[mi][3]);
            }
            #pragma unroll
            for (int njp = 0; njp < 4; njp++) {
                uint32_t toff = (uint32_t)((ks * 16 + t_krow) * VSTRIDE + warpN + njp * 16 + t_ncol) * 2;
                uint32_t vh[4], vl[4];
                ldsm_x4_t(vh, vb + PV_VHI + toff);
                ldsm_x4_t(vl, vb + PV_VLO + toff);
                #pragma unroll
                for (int h = 0; h < 2; h++)
                    #pragma unroll
                    for (int mi = 0; mi < 4; mi++)
                        mma16816(acc[mi][njp * 2 + h], ph[mi], &vh[h * 2]);
                #pragma unroll
                for (int h = 0; h < 2; h++)
                    #pragma unroll
                    for (int mi = 0; mi < 4; mi++)
                        mma16816(acc[mi][njp * 2 + h], ph[mi], &vl[h * 2]);
                #pragma unroll
                for (int h = 0; h < 2; h++)
                    #pragma unroll
                    for (int mi = 0; mi < 4; mi++)
                        mma16816(acc[mi][njp * 2 + h], pl[mi], &vh[h * 2]);
            }
        }
        __syncthreads();
    }

    #pragma unroll
    for (int mi = 0; mi < 4; mi++) {
        #pragma unroll
        for (int nj = 0; nj < 8; nj++) {
            int r0 = m0 + warpM + mi * 16 + (lid >> 2);
            int c0 = warpN + nj * 8 + (lid & 3) * 2;
            *(float2*)&o_out[((size_t)(b * NS) + r0) * ND + c0] =
                make_float2(acc[mi][nj][0], acc[mi][nj][1]);
            *(float2*)&o_out[((size_t)(b * NS) + r0 + 8) * ND + c0] =
                make_float2(acc[mi][nj][2], acc[mi][nj][3]);
        }
    }
}

// ---------------------------------------------------------------------------
extern "C" void kernel_launch(void* const* d_in, const int* in_sizes, int n_in,
                              void* d_out, int out_size)
{
    const float* X  = (const float*)d_in[0];
    const float* Wq = (const float*)d_in[1];
    const float* bq = (const float*)d_in[2];
    const float* Wk = (const float*)d_in[3];
    const float* bk = (const float*)d_in[4];
    const float* Wv = (const float*)d_in[5];
    const float* bv = (const float*)d_in[6];

    float* out   = (float*)d_out;                 // [32,1024,128]
    float* probs = out + (size_t)NB * NS * ND;    // [32,1024,1024]

    cudaFuncSetAttribute(qkv_mma_kernel, cudaFuncAttributeMaxDynamicSharedMemorySize, QK_SMEM);
    cudaFuncSetAttribute(score_kernel, cudaFuncAttributeMaxDynamicSharedMemorySize, SC_SMEM);
    cudaFuncSetAttribute(pv_kernel, cudaFuncAttributeMaxDynamicSharedMemorySize, PV_SMEM);

    convw_kernel<<<48, 256>>>(Wq, Wk, Wv);
    qkv_mma_kernel<<<dim3(3, 256), 128, QK_SMEM>>>(X, bq, bk, bv);
    score_kernel<<<dim3(8, 8, 32), 128, SC_SMEM>>>(probs);
    softmax_kernel<<<4096, 256>>>(probs);
    pv_kernel<<<dim3(8, 32), 128, PV_SMEM>>>(probs, out);
}

// round 12
// speedup vs baseline: 2.3723x; 1.8660x over previous
#include <cuda_runtime.h>
#include <cuda_fp16.h>
#include <cstdint>
#include <math.h>

#define NB 32
#define NS 1024
#define NH 1024
#define ND 128

// persistent scratch (__device__ globals per allocation rules) — fp16
__device__ __half g_q[NB * NS * ND];
__device__ __half g_k[NB * NS * ND];
__device__ __half g_v[NB * NS * ND];
__device__ __half g_wt[3 * ND * NH];   // [w][n][k] transposed weights

// ---------------------------------------------------------------------------
// helpers
// ---------------------------------------------------------------------------
__device__ __forceinline__ uint32_t smem_u32(const void* p) {
    uint32_t a;
    asm("{ .reg .u64 t; cvta.to.shared.u64 t, %1; cvt.u32.u64 %0, t; }" : "=r"(a) : "l"(p));
    return a;
}
__device__ __forceinline__ void ldsm_x4(uint32_t* r, uint32_t addr) {
    asm volatile("ldmatrix.sync.aligned.m8n8.x4.shared.b16 {%0,%1,%2,%3}, [%4];"
                 : "=r"(r[0]), "=r"(r[1]), "=r"(r[2]), "=r"(r[3]) : "r"(addr));
}
__device__ __forceinline__ void ldsm_x4_t(uint32_t* r, uint32_t addr) {
    asm volatile("ldmatrix.sync.aligned.m8n8.x4.trans.shared.b16 {%0,%1,%2,%3}, [%4];"
                 : "=r"(r[0]), "=r"(r[1]), "=r"(r[2]), "=r"(r[3]) : "r"(addr));
}
__device__ __forceinline__ void mma16816(float* d, const uint32_t* a, const uint32_t* b) {
    asm volatile(
        "mma.sync.aligned.m16n8k16.row.col.f32.f16.f16.f32 "
        "{%0,%1,%2,%3}, {%4,%5,%6,%7}, {%8,%9}, {%0,%1,%2,%3};"
        : "+f"(d[0]), "+f"(d[1]), "+f"(d[2]), "+f"(d[3])
        : "r"(a[0]), "r"(a[1]), "r"(a[2]), "r"(a[3]), "r"(b[0]), "r"(b[1]));
}
__device__ __forceinline__ uint32_t pack_h2(float a, float b) {
    __half2 h = __floats2half2_rn(a, b);
    return *(uint32_t*)&h;
}
__device__ __forceinline__ float fast_exp(float x) {
    float t = x * 1.4426950408889634f;
    int ii = __float2int_rn(t);
    float f = t - (float)ii;
    float y = f * 0.6931471805599453f;
    float p = 1.0f + y * (1.0f + y * (0.5f + y * (0.16666667f + y * (0.041666668f + y * 0.008333334f))));
    return __int_as_float(__float_as_int(p) + (ii << 23));
}
__device__ __forceinline__ void cp_async16(uint32_t smem_addr, const void* gptr) {
    asm volatile("cp.async.cg.shared.global [%0], [%1], 16;" :: "r"(smem_addr), "l"(gptr));
}
#define CP_COMMIT() asm volatile("cp.async.commit_group;" ::: "memory")
#define CP_WAIT(n)  asm volatile("cp.async.wait_group %0;" :: "n"(n) : "memory")

// ---------------------------------------------------------------------------
// Weight transpose to fp16: Wt[w][n][k] = fp16(W_w[k][n])
// ---------------------------------------------------------------------------
__global__ __launch_bounds__(256) void convw_kernel(
    const float* __restrict__ Wq, const float* __restrict__ Wk, const float* __restrict__ Wv)
{
    __shared__ float sW[64 * 129];
    int w = blockIdx.x >> 4;
    int k0 = (blockIdx.x & 15) * 64;
    const float* W = (w == 0) ? Wq : (w == 1) ? Wk : Wv;
    int tid = threadIdx.x;

    #pragma unroll
    for (int it = 0; it < 32; it++) {
        int f = tid + it * 256;
        int kk = f >> 7, n = f & 127;
        sW[kk * 129 + n] = W[(size_t)(k0 + kk) * ND + n];
    }
    __syncthreads();

    #pragma unroll
    for (int it = 0; it < 32; it++) {
        int f = tid + it * 256;
        int n = f >> 6, kk = f & 63;
        g_wt[(size_t)w * ND * NH + (size_t)n * NH + k0 + kk] =
            __float2half_rn(sW[kk * 129 + n]);
    }
}

// ---------------------------------------------------------------------------
// QKV GEMM: BM=128 BN=128 BK=32, 128 threads (4 warps 2x2, warp 64x64).
// A = X staged fp32 (cvt to fp16 frags inline); B = fp16 transposed weights.
// grid(3 w-fast, 256 m) so the 3 CTAs sharing an X tile co-run.
// ---------------------------------------------------------------------------
#define FSTRIDE 36                           // fp32 A/P smem stride (floats)
#define BSTRIDE 40                           // fp16 tile stride (elems)
#define QK_A   0                             // 128 x 36 fp32 = 18432 B
#define QK_B   18432                         // 128 x 40 fp16 = 10240 B
#define QK_STAGE 28672
#define QK_SMEM (2 * QK_STAGE)

__global__ __launch_bounds__(128, 2) void qkv_mma_kernel(
    const float* __restrict__ X,
    const float* __restrict__ bq, const float* __restrict__ bk, const float* __restrict__ bv)
{
    extern __shared__ char sm[];
    const uint32_t uS = smem_u32(sm);

    const int tid = threadIdx.x;
    const int wid = tid >> 5, lid = tid & 31;
    const int w  = blockIdx.x;
    const int m0 = blockIdx.y * 128;

    const __half* Wt = g_wt + (size_t)w * ND * NH;
    const float* bias = (w == 0) ? bq : (w == 1) ? bk : bv;
    __half* out = (w == 0) ? g_q : (w == 1) ? g_k : g_v;
    const float oscale = (w == 0) ? 0.08838834764831845f : 1.0f;

    const int warpM = (wid >> 1) * 64;       // 0, 64
    const int warpN = (wid & 1) * 64;        // 0, 64

    const int bx_row  = (lid & 7) + (lid >> 4) * 8;
    const int bx_koff = ((lid >> 3) & 1) * 8;
    const int p_row = lid >> 2;              // 0..7
    const int p_col = (lid & 3) * 2;         // 0,2,4,6

    float acc[4][8][4];
    #pragma unroll
    for (int i = 0; i < 4; i++)
        #pragma unroll
        for (int j = 0; j < 8; j++)
            #pragma unroll
            for (int c = 0; c < 4; c++) acc[i][j][c] = 0.f;

    auto issue_stage = [&](int kc, int s) {
        const int k0 = kc * 32;
        const uint32_t base = uS + s * QK_STAGE;
        // A: 128 rows x 32 fp32 = 1024 cp16
        #pragma unroll
        for (int it = 0; it < 8; it++) {
            int f = tid + it * 128;
            int row = f >> 3, u = f & 7;
            const float* src = X + (size_t)(m0 + row) * NH + k0 + u * 4;
            cp_async16(base + QK_A + (uint32_t)(row * FSTRIDE + u * 4) * 4, src);
        }
        // B: 128 rows x 32 fp16 = 512 cp16
        #pragma unroll
        for (int it = 0; it < 4; it++) {
            int f = tid + it * 128;
            int row = f >> 2, u = f & 3;
            const __half* src = Wt + (size_t)row * NH + k0 + u * 8;
            cp_async16(base + QK_B + (uint32_t)(row * BSTRIDE + u * 8) * 2, src);
        }
        CP_COMMIT();
    };

    issue_stage(0, 0);

    for (int kc = 0; kc < 32; kc++) {
        if (kc < 31) { issue_stage(kc + 1, (kc + 1) & 1); CP_WAIT(1); }
        else         { CP_WAIT(0); }
        __syncthreads();

        const float* Ab = (const float*)(sm + (kc & 1) * QK_STAGE + QK_A);
        const uint32_t bb = uS + (kc & 1) * QK_STAGE;

        #pragma unroll
        for (int ks = 0; ks < 2; ks++) {
            uint32_t ah[4][4];
            #pragma unroll
            for (int mi = 0; mi < 4; mi++) {
                int row  = warpM + mi * 16 + p_row;
                int kcol = ks * 16 + p_col;
                float2 p0 = *(const float2*)&Ab[row * FSTRIDE + kcol];
                float2 p1 = *(const float2*)&Ab[(row + 8) * FSTRIDE + kcol];
                float2 p2 = *(const float2*)&Ab[row * FSTRIDE + kcol + 8];
                float2 p3 = *(const float2*)&Ab[(row + 8) * FSTRIDE + kcol + 8];
                ah[mi][0] = pack_h2(p0.x, p0.y);
                ah[mi][1] = pack_h2(p1.x, p1.y);
                ah[mi][2] = pack_h2(p2.x, p2.y);
                ah[mi][3] = pack_h2(p3.x, p3.y);
            }
            #pragma unroll
            for (int njp = 0; njp < 4; njp++) {
                uint32_t boff = ((warpN + njp * 16 + bx_row) * BSTRIDE + ks * 16 + bx_koff) * 2;
                uint32_t bh[4];
                ldsm_x4(bh, bb + QK_B + boff);
                #pragma unroll
                for (int h = 0; h < 2; h++)
                    #pragma unroll
                    for (int mi = 0; mi < 4; mi++)
                        mma16816(acc[mi][njp * 2 + h], ah[mi], &bh[h * 2]);
            }
        }
        __syncthreads();
    }

    #pragma unroll
    for (int mi = 0; mi < 4; mi++) {
        #pragma unroll
        for (int nj = 0; nj < 8; nj++) {
            int r0 = m0 + warpM + mi * 16 + (lid >> 2);
            int c0 = warpN + nj * 8 + (lid & 3) * 2;
            float b0 = bias[c0], b1 = bias[c0 + 1];
            uint32_t h01 = pack_h2((acc[mi][nj][0] + b0) * oscale, (acc[mi][nj][1] + b1) * oscale);
            uint32_t h23 = pack_h2((acc[mi][nj][2] + b0) * oscale, (acc[mi][nj][3] + b1) * oscale);
            *(uint32_t*)&out[(size_t)r0 * ND + c0] = h01;
            *(uint32_t*)&out[(size_t)(r0 + 8) * ND + c0] = h23;
        }
    }
}

// ---------------------------------------------------------------------------
// score_kernel: raw S = q_scaled @ k^T -> probs buffer (fp32).
// 128 threads, 4 warps 2x2, warp 64x64, fp16 single-term.
// ---------------------------------------------------------------------------
#define SC_Q 0
#define SC_K 10240
#define SC_STAGE 20480
#define SC_SMEM (2 * SC_STAGE)

__global__ __launch_bounds__(128, 2) void score_kernel(float* __restrict__ probs)
{
    extern __shared__ char sm[];
    const uint32_t uS = smem_u32(sm);

    const int tid = threadIdx.x;
    const int wid = tid >> 5, lid = tid & 31;
    const int m0 = blockIdx.x * 128;
    const int n0 = blockIdx.y * 128;
    const int b  = blockIdx.z;
    const size_t qbase = (size_t)(b * NS + m0) * ND;
    const size_t kbase = (size_t)(b * NS + n0) * ND;

    const int warpM = (wid >> 1) * 64;
    const int warpN = (wid & 1) * 64;
    const int a_row  = lid & 15;
    const int a_koff = (lid >> 4) * 8;
    const int bx_row  = (lid & 7) + (lid >> 4) * 8;
    const int bx_koff = ((lid >> 3) & 1) * 8;

    float acc[4][8][4];
    #pragma unroll
    for (int i = 0; i < 4; i++)
        #pragma unroll
        for (int j = 0; j < 8; j++)
            #pragma unroll
            for (int c = 0; c < 4; c++) acc[i][j][c] = 0.f;

    auto issue_stage = [&](int kc, int s) {
        const int k0 = kc * 32;
        const uint32_t base = uS + s * SC_STAGE;
        // Q + K: 2 arrays x 128 rows x 32 fp16 = 1024 cp16
        #pragma unroll
        for (int it = 0; it < 8; it++) {
            int f = tid + it * 128;
            int arr = f >> 9;                // 0=Q,1=K
            int g = f & 511;
            int row = g >> 2, u = g & 3;
            const __half* src = (arr ? g_k + kbase : g_q + qbase) + (size_t)row * ND + k0 + u * 8;
            cp_async16(base + (arr ? SC_K : SC_Q) + (uint32_t)(row * BSTRIDE + u * 8) * 2, src);
        }
        CP_COMMIT();
    };

    issue_stage(0, 0);

    for (int kc = 0; kc < 4; kc++) {
        if (kc < 3) { issue_stage(kc + 1, (kc + 1) & 1); CP_WAIT(1); }
        else        { CP_WAIT(0); }
        __syncthreads();

        const uint32_t base = uS + (kc & 1) * SC_STAGE;
        #pragma unroll
        for (int ks = 0; ks < 2; ks++) {
            uint32_t ah[4][4];
            #pragma unroll
            for (int mi = 0; mi < 4; mi++) {
                uint32_t off = ((warpM + mi * 16 + a_row) * BSTRIDE + ks * 16 + a_koff) * 2;
                ldsm_x4(ah[mi], base + SC_Q + off);
            }
            #pragma unroll
            for (int njp = 0; njp < 4; njp++) {
                uint32_t boff = ((warpN + njp * 16 + bx_row) * BSTRIDE + ks * 16 + bx_koff) * 2;
                uint32_t bh[4];
                ldsm_x4(bh, base + SC_K + boff);
                #pragma unroll
                for (int h = 0; h < 2; h++)
                    #pragma unroll
                    for (int mi = 0; mi < 4; mi++)
                        mma16816(acc[mi][njp * 2 + h], ah[mi], &bh[h * 2]);
            }
        }
        __syncthreads();
    }

    float* pb = probs + (size_t)b * NS * NS;
    #pragma unroll
    for (int mi = 0; mi < 4; mi++) {
        #pragma unroll
        for (int nj = 0; nj < 8; nj++) {
            int r0 = m0 + warpM + mi * 16 + (lid >> 2);
            int c0 = n0 + warpN + nj * 8 + (lid & 3) * 2;
            *(float2*)&pb[(size_t)r0 * NS + c0]       = make_float2(acc[mi][nj][0], acc[mi][nj][1]);
            *(float2*)&pb[(size_t)(r0 + 8) * NS + c0] = make_float2(acc[mi][nj][2], acc[mi][nj][3]);
        }
    }
}

// ---------------------------------------------------------------------------
// softmax_kernel: warp per row, register resident; normalizes probs in place.
// ---------------------------------------------------------------------------
__global__ __launch_bounds__(256) void softmax_kernel(float* __restrict__ probs)
{
    const int wid = threadIdx.x >> 5, lid = threadIdx.x & 31;
    const int row = blockIdx.x * 8 + wid;
    const size_t base4 = (size_t)row * (NS / 4);

    float4 v[8];
    #pragma unroll
    for (int u = 0; u < 8; u++) v[u] = ((const float4*)probs)[base4 + lid + u * 32];

    float mx = -1e30f;
    #pragma unroll
    for (int u = 0; u < 8; u++) {
        mx = fmaxf(mx, fmaxf(fmaxf(v[u].x, v[u].y), fmaxf(v[u].z, v[u].w)));
    }
    #pragma unroll
    for (int o = 1; o < 32; o <<= 1) mx = fmaxf(mx, __shfl_xor_sync(0xffffffffu, mx, o));

    float sum = 0.f;
    #pragma unroll
    for (int u = 0; u < 8; u++) {
        v[u].x = fast_exp(v[u].x - mx);
        v[u].y = fast_exp(v[u].y - mx);
        v[u].z = fast_exp(v[u].z - mx);
        v[u].w = fast_exp(v[u].w - mx);
        sum += (v[u].x + v[u].y) + (v[u].z + v[u].w);
    }
    #pragma unroll
    for (int o = 1; o < 32; o <<= 1) sum += __shfl_xor_sync(0xffffffffu, sum, o);
    const float inv = 1.f / sum;

    #pragma unroll
    for (int u = 0; u < 8; u++) {
        v[u].x *= inv; v[u].y *= inv; v[u].z *= inv; v[u].w *= inv;
        ((float4*)probs)[base4 + lid + u * 32] = v[u];
    }
}

// ---------------------------------------------------------------------------
// pv_kernel: O = P @ V. 128 threads, 4 warps 2x2, warp 64x64, K=1024 BK=32.
// P staged fp32 (cvt inline); V fp16 (trans ldsm).
// ---------------------------------------------------------------------------
#define PV_P   0                             // 128 x 36 fp32 = 18432 B
#define PV_V   18432                         // 32 x 136 fp16 = 8704 B
#define PV_STAGE 27136
#define PV_SMEM (2 * PV_STAGE)
#define VSTRIDE 136

__global__ __launch_bounds__(128, 2) void pv_kernel(const float* __restrict__ probs,
                                                    float* __restrict__ o_out)
{
    extern __shared__ char sm[];
    const uint32_t uS = smem_u32(sm);

    const int tid = threadIdx.x;
    const int wid = tid >> 5, lid = tid & 31;
    const int m0 = blockIdx.x * 128;
    const int b  = blockIdx.y;
    const size_t pbase = (size_t)(b * NS + m0) * NS;
    const size_t vbase = (size_t)(b * NS) * ND;

    const int warpM = (wid >> 1) * 64;
    const int warpN = (wid & 1) * 64;
    const int t_krow = (lid & 7) + ((lid >> 3) & 1) * 8;
    const int t_ncol = (lid >> 4) * 8;
    const int p_row = lid >> 2;
    const int p_col = (lid & 3) * 2;

    float acc[4][8][4];
    #pragma unroll
    for (int i = 0; i < 4; i++)
        #pragma unroll
        for (int j = 0; j < 8; j++)
            #pragma unroll
            for (int c = 0; c < 4; c++) acc[i][j][c] = 0.f;

    auto issue_stage = [&](int kc, int s) {
        const int k0 = kc * 32;
        const uint32_t base = uS + s * PV_STAGE;
        // P: 128 rows x 32 fp32 = 1024 cp16
        #pragma unroll
        for (int it = 0; it < 8; it++) {
            int f = tid + it * 128;
            int row = f >> 3, u = f & 7;
            const float* src = probs + pbase + (size_t)row * NS + k0 + u * 4;
            cp_async16(base + PV_P + (uint32_t)(row * FSTRIDE + u * 4) * 4, src);
        }
        // V: 32 rows x 128 fp16 = 512 cp16
        #pragma unroll
        for (int it = 0; it < 4; it++) {
            int f = tid + it * 128;
            int row = f >> 4, u = f & 15;
            const __half* src = g_v + vbase + (size_t)(k0 + row) * ND + u * 8;
            cp_async16(base + PV_V + (uint32_t)(row * VSTRIDE + u * 8) * 2, src);
        }
        CP_COMMIT();
    };

    issue_stage(0, 0);

    for (int kc = 0; kc < 32; kc++) {
        if (kc < 31) { issue_stage(kc + 1, (kc + 1) & 1); CP_WAIT(1); }
        else         { CP_WAIT(0); }
        __syncthreads();

        const float* Pb = (const float*)(sm + (kc & 1) * PV_STAGE + PV_P);
        const uint32_t vb = uS + (kc & 1) * PV_STAGE;

        #pragma unroll
        for (int ks = 0; ks < 2; ks++) {
            uint32_t ph[4][4];
            #pragma unroll
            for (int mi = 0; mi < 4; mi++) {
                int row  = warpM + mi * 16 + p_row;
                int kcol = ks * 16 + p_col;
                float2 p0 = *(const float2*)&Pb[row * FSTRIDE + kcol];
                float2 p1 = *(const float2*)&Pb[(row + 8) * FSTRIDE + kcol];
                float2 p2 = *(const float2*)&Pb[row * FSTRIDE + kcol + 8];
                float2 p3 = *(const float2*)&Pb[(row + 8) * FSTRIDE + kcol + 8];
                ph[mi][0] = pack_h2(p0.x, p0.y);
                ph[mi][1] = pack_h2(p1.x, p1.y);
                ph[mi][2] = pack_h2(p2.x, p2.y);
                ph[mi][3] = pack_h2(p3.x, p3.y);
            }
            #pragma unroll
            for (int njp = 0; njp < 4; njp++) {
                uint32_t toff = (uint32_t)((ks * 16 + t_krow) * VSTRIDE + warpN + njp * 16 + t_ncol) * 2;
                uint32_t vh[4];
                ldsm_x4_t(vh, vb + PV_V + toff);
                #pragma unroll
                for (int h = 0; h < 2; h++)
                    #pragma unroll
                    for (int mi = 0; mi < 4; mi++)
                        mma16816(acc[mi][njp * 2 + h], ph[mi], &vh[h * 2]);
            }
        }
        __syncthreads();
    }

    #pragma unroll
    for (int mi = 0; mi < 4; mi++) {
        #pragma unroll
        for (int nj = 0; nj < 8; nj++) {
            int r0 = m0 + warpM + mi * 16 + (lid >> 2);
            int c0 = warpN + nj * 8 + (lid & 3) * 2;
            *(float2*)&o_out[((size_t)(b * NS) + r0) * ND + c0] =
                make_float2(acc[mi][nj][0], acc[mi][nj][1]);
            *(float2*)&o_out[((size_t)(b * NS) + r0 + 8) * ND + c0] =
                make_float2(acc[mi][nj][2], acc[mi][nj][3]);
        }
    }
}

// ---------------------------------------------------------------------------
extern "C" void kernel_launch(void* const* d_in, const int* in_sizes, int n_in,
                              void* d_out, int out_size)
{
    const float* X  = (const float*)d_in[0];
    const float* Wq = (const float*)d_in[1];
    const float* bq = (const float*)d_in[2];
    const float* Wk = (const float*)d_in[3];
    const float* bk = (const float*)d_in[4];
    const float* Wv = (const float*)d_in[5];
    const float* bv = (const float*)d_in[6];

    float* out   = (float*)d_out;                 // [32,1024,128]
    float* probs = out + (size_t)NB * NS * ND;    // [32,1024,1024]

    cudaFuncSetAttribute(qkv_mma_kernel, cudaFuncAttributeMaxDynamicSharedMemorySize, QK_SMEM);
    cudaFuncSetAttribute(score_kernel, cudaFuncAttributeMaxDynamicSharedMemorySize, SC_SMEM);
    cudaFuncSetAttribute(pv_kernel, cudaFuncAttributeMaxDynamicSharedMemorySize, PV_SMEM);

    convw_kernel<<<48, 256>>>(Wq, Wk, Wv);
    qkv_mma_kernel<<<dim3(3, 256), 128, QK_SMEM>>>(X, bq, bk, bv);
    score_kernel<<<dim3(8, 8, 32), 128, SC_SMEM>>>(probs);
    softmax_kernel<<<4096, 256>>>(probs);
    pv_kernel<<<dim3(8, 32), 128, PV_SMEM>>>(probs, out);
}

// round 13
// speedup vs baseline: 2.4943x; 1.0514x over previous
#include <cuda_runtime.h>
#include <cuda_fp16.h>
#include <cstdint>
#include <math.h>

#define NB 32
#define NS 1024
#define NH 1024
#define ND 128

// persistent scratch (__device__ globals per allocation rules) — fp16
__device__ __half g_q[NB * NS * ND];
__device__ __half g_k[NB * NS * ND];
__device__ __half g_v[NB * NS * ND];
__device__ __half g_wt[3 * ND * NH];   // [w][n][k] transposed weights
__device__ float  g_sums[NB * NS];     // per-row exp sums (atomic)

// ---------------------------------------------------------------------------
// helpers
// ---------------------------------------------------------------------------
__device__ __forceinline__ uint32_t smem_u32(const void* p) {
    uint32_t a;
    asm("{ .reg .u64 t; cvta.to.shared.u64 t, %1; cvt.u32.u64 %0, t; }" : "=r"(a) : "l"(p));
    return a;
}
__device__ __forceinline__ void ldsm_x4(uint32_t* r, uint32_t addr) {
    asm volatile("ldmatrix.sync.aligned.m8n8.x4.shared.b16 {%0,%1,%2,%3}, [%4];"
                 : "=r"(r[0]), "=r"(r[1]), "=r"(r[2]), "=r"(r[3]) : "r"(addr));
}
__device__ __forceinline__ void ldsm_x4_t(uint32_t* r, uint32_t addr) {
    asm volatile("ldmatrix.sync.aligned.m8n8.x4.trans.shared.b16 {%0,%1,%2,%3}, [%4];"
                 : "=r"(r[0]), "=r"(r[1]), "=r"(r[2]), "=r"(r[3]) : "r"(addr));
}
__device__ __forceinline__ void mma16816(float* d, const uint32_t* a, const uint32_t* b) {
    asm volatile(
        "mma.sync.aligned.m16n8k16.row.col.f32.f16.f16.f32 "
        "{%0,%1,%2,%3}, {%4,%5,%6,%7}, {%8,%9}, {%0,%1,%2,%3};"
        : "+f"(d[0]), "+f"(d[1]), "+f"(d[2]), "+f"(d[3])
        : "r"(a[0]), "r"(a[1]), "r"(a[2]), "r"(a[3]), "r"(b[0]), "r"(b[1]));
}
__device__ __forceinline__ uint32_t pack_h2(float a, float b) {
    __half2 h = __floats2half2_rn(a, b);
    return *(uint32_t*)&h;
}
__device__ __forceinline__ float fast_exp(float x) {
    float t = x * 1.4426950408889634f;
    int ii = __float2int_rn(t);
    float f = t - (float)ii;
    float y = f * 0.6931471805599453f;
    float p = 1.0f + y * (1.0f + y * (0.5f + y * (0.16666667f + y * (0.041666668f + y * 0.008333334f))));
    return __int_as_float(__float_as_int(p) + (ii << 23));
}
__device__ __forceinline__ void cp_async16(uint32_t smem_addr, const void* gptr) {
    asm volatile("cp.async.cg.shared.global [%0], [%1], 16;" :: "r"(smem_addr), "l"(gptr));
}
#define CP_COMMIT() asm volatile("cp.async.commit_group;" ::: "memory")
#define CP_WAIT(n)  asm volatile("cp.async.wait_group %0;" :: "n"(n) : "memory")

// ---------------------------------------------------------------------------
// Weight transpose to fp16 + zero g_sums (runs every replay)
// ---------------------------------------------------------------------------
__global__ __launch_bounds__(256) void convw_kernel(
    const float* __restrict__ Wq, const float* __restrict__ Wk, const float* __restrict__ Wv)
{
    __shared__ float sW[64 * 129];
    int w = blockIdx.x >> 4;
    int k0 = (blockIdx.x & 15) * 64;
    const float* W = (w == 0) ? Wq : (w == 1) ? Wk : Wv;
    int tid = threadIdx.x;

    // zero the exp-sum accumulators
    for (int i = blockIdx.x * 256 + tid; i < NB * NS; i += gridDim.x * 256)
        g_sums[i] = 0.f;

    #pragma unroll
    for (int it = 0; it < 32; it++) {
        int f = tid + it * 256;
        int kk = f >> 7, n = f & 127;
        sW[kk * 129 + n] = W[(size_t)(k0 + kk) * ND + n];
    }
    __syncthreads();

    #pragma unroll
    for (int it = 0; it < 32; it++) {
        int f = tid + it * 256;
        int n = f >> 6, kk = f & 63;
        g_wt[(size_t)w * ND * NH + (size_t)n * NH + k0 + kk] =
            __float2half_rn(sW[kk * 129 + n]);
    }
}

// ---------------------------------------------------------------------------
// QKV GEMM: BM=128 BN=128 BK=32, 128 threads (4 warps 2x2, warp 64x64).
// ---------------------------------------------------------------------------
#define FSTRIDE 36                           // fp32 A/P smem stride (floats)
#define BSTRIDE 40                           // fp16 tile stride (elems)
#define QK_A   0                             // 128 x 36 fp32 = 18432 B
#define QK_B   18432                         // 128 x 40 fp16 = 10240 B
#define QK_STAGE 28672
#define QK_SMEM (2 * QK_STAGE)

__global__ __launch_bounds__(128, 2) void qkv_mma_kernel(
    const float* __restrict__ X,
    const float* __restrict__ bq, const float* __restrict__ bk, const float* __restrict__ bv)
{
    extern __shared__ char sm[];
    const uint32_t uS = smem_u32(sm);

    const int tid = threadIdx.x;
    const int wid = tid >> 5, lid = tid & 31;
    const int w  = blockIdx.x;
    const int m0 = blockIdx.y * 128;

    const __half* Wt = g_wt + (size_t)w * ND * NH;
    const float* bias = (w == 0) ? bq : (w == 1) ? bk : bv;
    __half* out = (w == 0) ? g_q : (w == 1) ? g_k : g_v;
    const float oscale = (w == 0) ? 0.08838834764831845f : 1.0f;

    const int warpM = (wid >> 1) * 64;
    const int warpN = (wid & 1) * 64;

    const int bx_row  = (lid & 7) + (lid >> 4) * 8;
    const int bx_koff = ((lid >> 3) & 1) * 8;
    const int p_row = lid >> 2;
    const int p_col = (lid & 3) * 2;

    float acc[4][8][4];
    #pragma unroll
    for (int i = 0; i < 4; i++)
        #pragma unroll
        for (int j = 0; j < 8; j++)
            #pragma unroll
            for (int c = 0; c < 4; c++) acc[i][j][c] = 0.f;

    auto issue_stage = [&](int kc, int s) {
        const int k0 = kc * 32;
        const uint32_t base = uS + s * QK_STAGE;
        #pragma unroll
        for (int it = 0; it < 8; it++) {
            int f = tid + it * 128;
            int row = f >> 3, u = f & 7;
            const float* src = X + (size_t)(m0 + row) * NH + k0 + u * 4;
            cp_async16(base + QK_A + (uint32_t)(row * FSTRIDE + u * 4) * 4, src);
        }
        #pragma unroll
        for (int it = 0; it < 4; it++) {
            int f = tid + it * 128;
            int row = f >> 2, u = f & 3;
            const __half* src = Wt + (size_t)row * NH + k0 + u * 8;
            cp_async16(base + QK_B + (uint32_t)(row * BSTRIDE + u * 8) * 2, src);
        }
        CP_COMMIT();
    };

    issue_stage(0, 0);

    for (int kc = 0; kc < 32; kc++) {
        if (kc < 31) { issue_stage(kc + 1, (kc + 1) & 1); CP_WAIT(1); }
        else         { CP_WAIT(0); }
        __syncthreads();

        const float* Ab = (const float*)(sm + (kc & 1) * QK_STAGE + QK_A);
        const uint32_t bb = uS + (kc & 1) * QK_STAGE;

        #pragma unroll
        for (int ks = 0; ks < 2; ks++) {
            uint32_t ah[4][4];
            #pragma unroll
            for (int mi = 0; mi < 4; mi++) {
                int row  = warpM + mi * 16 + p_row;
                int kcol = ks * 16 + p_col;
                float2 p0 = *(const float2*)&Ab[row * FSTRIDE + kcol];
                float2 p1 = *(const float2*)&Ab[(row + 8) * FSTRIDE + kcol];
                float2 p2 = *(const float2*)&Ab[row * FSTRIDE + kcol + 8];
                float2 p3 = *(const float2*)&Ab[(row + 8) * FSTRIDE + kcol + 8];
                ah[mi][0] = pack_h2(p0.x, p0.y);
                ah[mi][1] = pack_h2(p1.x, p1.y);
                ah[mi][2] = pack_h2(p2.x, p2.y);
                ah[mi][3] = pack_h2(p3.x, p3.y);
            }
            #pragma unroll
            for (int njp = 0; njp < 4; njp++) {
                uint32_t boff = ((warpN + njp * 16 + bx_row) * BSTRIDE + ks * 16 + bx_koff) * 2;
                uint32_t bh[4];
                ldsm_x4(bh, bb + QK_B + boff);
                #pragma unroll
                for (int h = 0; h < 2; h++)
                    #pragma unroll
                    for (int mi = 0; mi < 4; mi++)
                        mma16816(acc[mi][njp * 2 + h], ah[mi], &bh[h * 2]);
            }
        }
        __syncthreads();
    }

    #pragma unroll
    for (int mi = 0; mi < 4; mi++) {
        #pragma unroll
        for (int nj = 0; nj < 8; nj++) {
            int r0 = m0 + warpM + mi * 16 + (lid >> 2);
            int c0 = warpN + nj * 8 + (lid & 3) * 2;
            float b0 = bias[c0], b1 = bias[c0 + 1];
            uint32_t h01 = pack_h2((acc[mi][nj][0] + b0) * oscale, (acc[mi][nj][1] + b1) * oscale);
            uint32_t h23 = pack_h2((acc[mi][nj][2] + b0) * oscale, (acc[mi][nj][3] + b1) * oscale);
            *(uint32_t*)&out[(size_t)r0 * ND + c0] = h01;
            *(uint32_t*)&out[(size_t)(r0 + 8) * ND + c0] = h23;
        }
    }
}

// ---------------------------------------------------------------------------
// score_kernel: writes exp(S) (unnormalized) + atomic per-row exp-sums.
// 128 threads, 4 warps 2x2, warp 64x64, fp16 single-term.
// ---------------------------------------------------------------------------
#define SC_Q 0
#define SC_K 10240
#define SC_STAGE 20480
#define SC_SMEM (2 * SC_STAGE)

__global__ __launch_bounds__(128, 2) void score_kernel(float* __restrict__ probs)
{
    extern __shared__ char sm[];
    const uint32_t uS = smem_u32(sm);

    const int tid = threadIdx.x;
    const int wid = tid >> 5, lid = tid & 31;
    const int m0 = blockIdx.x * 128;
    const int n0 = blockIdx.y * 128;
    const int b  = blockIdx.z;
    const size_t qbase = (size_t)(b * NS + m0) * ND;
    const size_t kbase = (size_t)(b * NS + n0) * ND;

    const int warpM = (wid >> 1) * 64;
    const int warpN = (wid & 1) * 64;
    const int a_row  = lid & 15;
    const int a_koff = (lid >> 4) * 8;
    const int bx_row  = (lid & 7) + (lid >> 4) * 8;
    const int bx_koff = ((lid >> 3) & 1) * 8;

    float acc[4][8][4];
    #pragma unroll
    for (int i = 0; i < 4; i++)
        #pragma unroll
        for (int j = 0; j < 8; j++)
            #pragma unroll
            for (int c = 0; c < 4; c++) acc[i][j][c] = 0.f;

    auto issue_stage = [&](int kc, int s) {
        const int k0 = kc * 32;
        const uint32_t base = uS + s * SC_STAGE;
        #pragma unroll
        for (int it = 0; it < 8; it++) {
            int f = tid + it * 128;
            int arr = f >> 9;
            int g = f & 511;
            int row = g >> 2, u = g & 3;
            const __half* src = (arr ? g_k + kbase : g_q + qbase) + (size_t)row * ND + k0 + u * 8;
            cp_async16(base + (arr ? SC_K : SC_Q) + (uint32_t)(row * BSTRIDE + u * 8) * 2, src);
        }
        CP_COMMIT();
    };

    issue_stage(0, 0);

    for (int kc = 0; kc < 4; kc++) {
        if (kc < 3) { issue_stage(kc + 1, (kc + 1) & 1); CP_WAIT(1); }
        else        { CP_WAIT(0); }
        __syncthreads();

        const uint32_t base = uS + (kc & 1) * SC_STAGE;
        #pragma unroll
        for (int ks = 0; ks < 2; ks++) {
            uint32_t ah[4][4];
            #pragma unroll
            for (int mi = 0; mi < 4; mi++) {
                uint32_t off = ((warpM + mi * 16 + a_row) * BSTRIDE + ks * 16 + a_koff) * 2;
                ldsm_x4(ah[mi], base + SC_Q + off);
            }
            #pragma unroll
            for (int njp = 0; njp < 4; njp++) {
                uint32_t boff = ((warpN + njp * 16 + bx_row) * BSTRIDE + ks * 16 + bx_koff) * 2;
                uint32_t bh[4];
                ldsm_x4(bh, base + SC_K + boff);
                #pragma unroll
                for (int h = 0; h < 2; h++)
                    #pragma unroll
                    for (int mi = 0; mi < 4; mi++)
                        mma16816(acc[mi][njp * 2 + h], ah[mi], &bh[h * 2]);
            }
        }
        __syncthreads();
    }

    // epilogue: exp, write unnormalized, accumulate row sums (shfl + atomic)
    float* pb = probs + (size_t)b * NS * NS;
    #pragma unroll
    for (int mi = 0; mi < 4; mi++) {
        int r0 = m0 + warpM + mi * 16 + (lid >> 2);
        float rs0 = 0.f, rs1 = 0.f;
        #pragma unroll
        for (int nj = 0; nj < 8; nj++) {
            int c0 = n0 + warpN + nj * 8 + (lid & 3) * 2;
            float e0 = fast_exp(acc[mi][nj][0]);
            float e1 = fast_exp(acc[mi][nj][1]);
            float e2 = fast_exp(acc[mi][nj][2]);
            float e3 = fast_exp(acc[mi][nj][3]);
            *(float2*)&pb[(size_t)r0 * NS + c0]       = make_float2(e0, e1);
            *(float2*)&pb[(size_t)(r0 + 8) * NS + c0] = make_float2(e2, e3);
            rs0 += e0 + e1;
            rs1 += e2 + e3;
        }
        rs0 += __shfl_xor_sync(0xffffffffu, rs0, 1);
        rs0 += __shfl_xor_sync(0xffffffffu, rs0, 2);
        rs1 += __shfl_xor_sync(0xffffffffu, rs1, 1);
        rs1 += __shfl_xor_sync(0xffffffffu, rs1, 2);
        if ((lid & 3) == 0) {
            atomicAdd(&g_sums[b * NS + r0], rs0);
            atomicAdd(&g_sums[b * NS + r0 + 8], rs1);
        }
    }
}

// ---------------------------------------------------------------------------
// pv_kernel: O = (expS @ V) * inv_sum; also writes normalized probs back.
// 128 threads, 4 warps 2x2, warp 64x64, K=1024 BK=32.
// ---------------------------------------------------------------------------
#define PV_P   0                             // 128 x 36 fp32 = 18432 B
#define PV_V   18432                         // 32 x 136 fp16 = 8704 B
#define PV_STAGE 27136
#define PV_SMEM (2 * PV_STAGE)
#define VSTRIDE 136

__global__ __launch_bounds__(128, 2) void pv_kernel(float* __restrict__ probs,
                                                    float* __restrict__ o_out)
{
    extern __shared__ char sm[];
    __shared__ float s_inv[128];
    const uint32_t uS = smem_u32(sm);

    const int tid = threadIdx.x;
    const int wid = tid >> 5, lid = tid & 31;
    const int m0 = blockIdx.x * 128;
    const int b  = blockIdx.y;
    const size_t pbase = (size_t)(b * NS + m0) * NS;
    const size_t vbase = (size_t)(b * NS) * ND;

    const int warpM = (wid >> 1) * 64;
    const int warpN = (wid & 1) * 64;
    const int t_krow = (lid & 7) + ((lid >> 3) & 1) * 8;
    const int t_ncol = (lid >> 4) * 8;
    const int p_row = lid >> 2;
    const int p_col = (lid & 3) * 2;

    // per-row inverse sums
    s_inv[tid] = 1.0f / g_sums[b * NS + m0 + tid];

    float acc[4][8][4];
    #pragma unroll
    for (int i = 0; i < 4; i++)
        #pragma unroll
        for (int j = 0; j < 8; j++)
            #pragma unroll
            for (int c = 0; c < 4; c++) acc[i][j][c] = 0.f;

    auto issue_stage = [&](int kc, int s) {
        const int k0 = kc * 32;
        const uint32_t base = uS + s * PV_STAGE;
        #pragma unroll
        for (int it = 0; it < 8; it++) {
            int f = tid + it * 128;
            int row = f >> 3, u = f & 7;
            const float* src = probs + pbase + (size_t)row * NS + k0 + u * 4;
            cp_async16(base + PV_P + (uint32_t)(row * FSTRIDE + u * 4) * 4, src);
        }
        #pragma unroll
        for (int it = 0; it < 4; it++) {
            int f = tid + it * 128;
            int row = f >> 4, u = f & 15;
            const __half* src = g_v + vbase + (size_t)(k0 + row) * ND + u * 8;
            cp_async16(base + PV_V + (uint32_t)(row * VSTRIDE + u * 8) * 2, src);
        }
        CP_COMMIT();
    };

    issue_stage(0, 0);
    __syncthreads();   // s_inv visible

    float inv0[4], inv1[4];
    #pragma unroll
    for (int mi = 0; mi < 4; mi++) {
        inv0[mi] = s_inv[warpM + mi * 16 + p_row];
        inv1[mi] = s_inv[warpM + mi * 16 + p_row + 8];
    }

    for (int kc = 0; kc < 32; kc++) {
        if (kc < 31) { issue_stage(kc + 1, (kc + 1) & 1); CP_WAIT(1); }
        else         { CP_WAIT(0); }
        __syncthreads();

        const float* Pb = (const float*)(sm + (kc & 1) * PV_STAGE + PV_P);
        const uint32_t vb = uS + (kc & 1) * PV_STAGE;
        const int k0c = kc * 32;

        #pragma unroll
        for (int ks = 0; ks < 2; ks++) {
            uint32_t ph[4][4];
            #pragma unroll
            for (int mi = 0; mi < 4; mi++) {
                int row  = warpM + mi * 16 + p_row;
                int kcol = ks * 16 + p_col;
                float2 p0 = *(const float2*)&Pb[row * FSTRIDE + kcol];
                float2 p1 = *(const float2*)&Pb[(row + 8) * FSTRIDE + kcol];
                float2 p2 = *(const float2*)&Pb[row * FSTRIDE + kcol + 8];
                float2 p3 = *(const float2*)&Pb[(row + 8) * FSTRIDE + kcol + 8];
                ph[mi][0] = pack_h2(p0.x * inv0[mi], p0.y * inv0[mi]);
                ph[mi][1] = pack_h2(p1.x * inv1[mi], p1.y * inv1[mi]);
                ph[mi][2] = pack_h2(p2.x * inv0[mi], p2.y * inv0[mi]);
                ph[mi][3] = pack_h2(p3.x * inv1[mi], p3.y * inv1[mi]);
            }
            #pragma unroll
            for (int njp = 0; njp < 4; njp++) {
                uint32_t toff = (uint32_t)((ks * 16 + t_krow) * VSTRIDE + warpN + njp * 16 + t_ncol) * 2;
                uint32_t vh[4];
                ldsm_x4_t(vh, vb + PV_V + toff);
                #pragma unroll
                for (int h = 0; h < 2; h++)
                    #pragma unroll
                    for (int mi = 0; mi < 4; mi++)
                        mma16816(acc[mi][njp * 2 + h], ph[mi], &vh[h * 2]);
            }
        }

        // write normalized probs chunk back (required output)
        #pragma unroll
        for (int it = 0; it < 8; it++) {
            int f = tid + it * 128;
            int row = f >> 3, u = f & 7;
            float4 v = *(const float4*)&Pb[row * FSTRIDE + u * 4];
            float iv = s_inv[row];
            v.x *= iv; v.y *= iv; v.z *= iv; v.w *= iv;
            *(float4*)&probs[pbase + (size_t)row * NS + k0c + u * 4] = v;
        }
        __syncthreads();
    }

    #pragma unroll
    for (int mi = 0; mi < 4; mi++) {
        #pragma unroll
        for (int nj = 0; nj < 8; nj++) {
            int r0 = m0 + warpM + mi * 16 + (lid >> 2);
            int c0 = warpN + nj * 8 + (lid & 3) * 2;
            *(float2*)&o_out[((size_t)(b * NS) + r0) * ND + c0] =
                make_float2(acc[mi][nj][0], acc[mi][nj][1]);
            *(float2*)&o_out[((size_t)(b * NS) + r0 + 8) * ND + c0] =
                make_float2(acc[mi][nj][2], acc[mi][nj][3]);
        }
    }
}

// ---------------------------------------------------------------------------
extern "C" void kernel_launch(void* const* d_in, const int* in_sizes, int n_in,
                              void* d_out, int out_size)
{
    const float* X  = (const float*)d_in[0];
    const float* Wq = (const float*)d_in[1];
    const float* bq = (const float*)d_in[2];
    const float* Wk = (const float*)d_in[3];
    const float* bk = (const float*)d_in[4];
    const float* Wv = (const float*)d_in[5];
    const float* bv = (const float*)d_in[6];

    float* out   = (float*)d_out;                 // [32,1024,128]
    float* probs = out + (size_t)NB * NS * ND;    // [32,1024,1024]

    cudaFuncSetAttribute(qkv_mma_kernel, cudaFuncAttributeMaxDynamicSharedMemorySize, QK_SMEM);
    cudaFuncSetAttribute(score_kernel, cudaFuncAttributeMaxDynamicSharedMemorySize, SC_SMEM);
    cudaFuncSetAttribute(pv_kernel, cudaFuncAttributeMaxDynamicSharedMemorySize, PV_SMEM);

    convw_kernel<<<48, 256>>>(Wq, Wk, Wv);
    qkv_mma_kernel<<<dim3(3, 256), 128, QK_SMEM>>>(X, bq, bk, bv);
    score_kernel<<<dim3(8, 8, 32), 128, SC_SMEM>>>(probs);
    pv_kernel<<<dim3(8, 32), 128, PV_SMEM>>>(probs, out);
}

// round 14
// speedup vs baseline: 2.5526x; 1.0234x over previous
#include <cuda_runtime.h>
#include <cuda_fp16.h>
#include <cstdint>
#include <math.h>

#define NB 32
#define NS 1024
#define NH 1024
#define ND 128

// persistent scratch (__device__ globals per allocation rules) — fp16
__device__ __half g_q[NB * NS * ND];
__device__ __half g_k[NB * NS * ND];
__device__ __half g_v[NB * NS * ND];
__device__ __half g_pe[NB * NS * NS];  // unnormalized exp(S), fp16
__device__ __half g_wt[3 * ND * NH];   // [w][n][k] transposed weights
__device__ float  g_sums[NB * NS];     // per-row exp sums (atomic)

// ---------------------------------------------------------------------------
// helpers
// ---------------------------------------------------------------------------
__device__ __forceinline__ uint32_t smem_u32(const void* p) {
    uint32_t a;
    asm("{ .reg .u64 t; cvta.to.shared.u64 t, %1; cvt.u32.u64 %0, t; }" : "=r"(a) : "l"(p));
    return a;
}
__device__ __forceinline__ void ldsm_x4(uint32_t* r, uint32_t addr) {
    asm volatile("ldmatrix.sync.aligned.m8n8.x4.shared.b16 {%0,%1,%2,%3}, [%4];"
                 : "=r"(r[0]), "=r"(r[1]), "=r"(r[2]), "=r"(r[3]) : "r"(addr));
}
__device__ __forceinline__ void ldsm_x4_t(uint32_t* r, uint32_t addr) {
    asm volatile("ldmatrix.sync.aligned.m8n8.x4.trans.shared.b16 {%0,%1,%2,%3}, [%4];"
                 : "=r"(r[0]), "=r"(r[1]), "=r"(r[2]), "=r"(r[3]) : "r"(addr));
}
__device__ __forceinline__ void mma16816(float* d, const uint32_t* a, const uint32_t* b) {
    asm volatile(
        "mma.sync.aligned.m16n8k16.row.col.f32.f16.f16.f32 "
        "{%0,%1,%2,%3}, {%4,%5,%6,%7}, {%8,%9}, {%0,%1,%2,%3};"
        : "+f"(d[0]), "+f"(d[1]), "+f"(d[2]), "+f"(d[3])
        : "r"(a[0]), "r"(a[1]), "r"(a[2]), "r"(a[3]), "r"(b[0]), "r"(b[1]));
}
__device__ __forceinline__ uint32_t pack_h2(float a, float b) {
    __half2 h = __floats2half2_rn(a, b);
    return *(uint32_t*)&h;
}
__device__ __forceinline__ float fast_exp(float x) {
    float t = x * 1.4426950408889634f;
    int ii = __float2int_rn(t);
    float f = t - (float)ii;
    float y = f * 0.6931471805599453f;
    float p = 1.0f + y * (1.0f + y * (0.5f + y * (0.16666667f + y * (0.041666668f + y * 0.008333334f))));
    return __int_as_float(__float_as_int(p) + (ii << 23));
}
__device__ __forceinline__ void cp_async16(uint32_t smem_addr, const void* gptr) {
    asm volatile("cp.async.cg.shared.global [%0], [%1], 16;" :: "r"(smem_addr), "l"(gptr));
}
#define CP_COMMIT() asm volatile("cp.async.commit_group;" ::: "memory")
#define CP_WAIT(n)  asm volatile("cp.async.wait_group %0;" :: "n"(n) : "memory")

// ---------------------------------------------------------------------------
// Weight transpose to fp16 + zero g_sums (runs every replay)
// ---------------------------------------------------------------------------
__global__ __launch_bounds__(256) void convw_kernel(
    const float* __restrict__ Wq, const float* __restrict__ Wk, const float* __restrict__ Wv)
{
    __shared__ float sW[64 * 129];
    int w = blockIdx.x >> 4;
    int k0 = (blockIdx.x & 15) * 64;
    const float* W = (w == 0) ? Wq : (w == 1) ? Wk : Wv;
    int tid = threadIdx.x;

    for (int i = blockIdx.x * 256 + tid; i < NB * NS; i += gridDim.x * 256)
        g_sums[i] = 0.f;

    #pragma unroll
    for (int it = 0; it < 32; it++) {
        int f = tid + it * 256;
        int kk = f >> 7, n = f & 127;
        sW[kk * 129 + n] = W[(size_t)(k0 + kk) * ND + n];
    }
    __syncthreads();

    #pragma unroll
    for (int it = 0; it < 32; it++) {
        int f = tid + it * 256;
        int n = f >> 6, kk = f & 63;
        g_wt[(size_t)w * ND * NH + (size_t)n * NH + k0 + kk] =
            __float2half_rn(sW[kk * 129 + n]);
    }
}

// ---------------------------------------------------------------------------
// QKV GEMM: BM=128 BN=128 BK=32, 128 threads (4 warps 2x2, warp 64x64).
// ---------------------------------------------------------------------------
#define FSTRIDE 36
#define BSTRIDE 40
#define QK_A   0                             // 128 x 36 fp32 = 18432 B
#define QK_B   18432                         // 128 x 40 fp16 = 10240 B
#define QK_STAGE 28672
#define QK_SMEM (2 * QK_STAGE)

__global__ __launch_bounds__(128, 2) void qkv_mma_kernel(
    const float* __restrict__ X,
    const float* __restrict__ bq, const float* __restrict__ bk, const float* __restrict__ bv)
{
    extern __shared__ char sm[];
    const uint32_t uS = smem_u32(sm);

    const int tid = threadIdx.x;
    const int wid = tid >> 5, lid = tid & 31;
    const int w  = blockIdx.x;
    const int m0 = blockIdx.y * 128;

    const __half* Wt = g_wt + (size_t)w * ND * NH;
    const float* bias = (w == 0) ? bq : (w == 1) ? bk : bv;
    __half* out = (w == 0) ? g_q : (w == 1) ? g_k : g_v;
    const float oscale = (w == 0) ? 0.08838834764831845f : 1.0f;

    const int warpM = (wid >> 1) * 64;
    const int warpN = (wid & 1) * 64;

    const int bx_row  = (lid & 7) + (lid >> 4) * 8;
    const int bx_koff = ((lid >> 3) & 1) * 8;
    const int p_row = lid >> 2;
    const int p_col = (lid & 3) * 2;

    float acc[4][8][4];
    #pragma unroll
    for (int i = 0; i < 4; i++)
        #pragma unroll
        for (int j = 0; j < 8; j++)
            #pragma unroll
            for (int c = 0; c < 4; c++) acc[i][j][c] = 0.f;

    auto issue_stage = [&](int kc, int s) {
        const int k0 = kc * 32;
        const uint32_t base = uS + s * QK_STAGE;
        #pragma unroll
        for (int it = 0; it < 8; it++) {
            int f = tid + it * 128;
            int row = f >> 3, u = f & 7;
            const float* src = X + (size_t)(m0 + row) * NH + k0 + u * 4;
            cp_async16(base + QK_A + (uint32_t)(row * FSTRIDE + u * 4) * 4, src);
        }
        #pragma unroll
        for (int it = 0; it < 4; it++) {
            int f = tid + it * 128;
            int row = f >> 2, u = f & 3;
            const __half* src = Wt + (size_t)row * NH + k0 + u * 8;
            cp_async16(base + QK_B + (uint32_t)(row * BSTRIDE + u * 8) * 2, src);
        }
        CP_COMMIT();
    };

    issue_stage(0, 0);

    for (int kc = 0; kc < 32; kc++) {
        if (kc < 31) { issue_stage(kc + 1, (kc + 1) & 1); CP_WAIT(1); }
        else         { CP_WAIT(0); }
        __syncthreads();

        const float* Ab = (const float*)(sm + (kc & 1) * QK_STAGE + QK_A);
        const uint32_t bb = uS + (kc & 1) * QK_STAGE;

        #pragma unroll
        for (int ks = 0; ks < 2; ks++) {
            uint32_t ah[4][4];
            #pragma unroll
            for (int mi = 0; mi < 4; mi++) {
                int row  = warpM + mi * 16 + p_row;
                int kcol = ks * 16 + p_col;
                float2 p0 = *(const float2*)&Ab[row * FSTRIDE + kcol];
                float2 p1 = *(const float2*)&Ab[(row + 8) * FSTRIDE + kcol];
                float2 p2 = *(const float2*)&Ab[row * FSTRIDE + kcol + 8];
                float2 p3 = *(const float2*)&Ab[(row + 8) * FSTRIDE + kcol + 8];
                ah[mi][0] = pack_h2(p0.x, p0.y);
                ah[mi][1] = pack_h2(p1.x, p1.y);
                ah[mi][2] = pack_h2(p2.x, p2.y);
                ah[mi][3] = pack_h2(p3.x, p3.y);
            }
            #pragma unroll
            for (int njp = 0; njp < 4; njp++) {
                uint32_t boff = ((warpN + njp * 16 + bx_row) * BSTRIDE + ks * 16 + bx_koff) * 2;
                uint32_t bh[4];
                ldsm_x4(bh, bb + QK_B + boff);
                #pragma unroll
                for (int h = 0; h < 2; h++)
                    #pragma unroll
                    for (int mi = 0; mi < 4; mi++)
                        mma16816(acc[mi][njp * 2 + h], ah[mi], &bh[h * 2]);
            }
        }
        __syncthreads();
    }

    #pragma unroll
    for (int mi = 0; mi < 4; mi++) {
        #pragma unroll
        for (int nj = 0; nj < 8; nj++) {
            int r0 = m0 + warpM + mi * 16 + (lid >> 2);
            int c0 = warpN + nj * 8 + (lid & 3) * 2;
            float b0 = bias[c0], b1 = bias[c0 + 1];
            uint32_t h01 = pack_h2((acc[mi][nj][0] + b0) * oscale, (acc[mi][nj][1] + b1) * oscale);
            uint32_t h23 = pack_h2((acc[mi][nj][2] + b0) * oscale, (acc[mi][nj][3] + b1) * oscale);
            *(uint32_t*)&out[(size_t)r0 * ND + c0] = h01;
            *(uint32_t*)&out[(size_t)(r0 + 8) * ND + c0] = h23;
        }
    }
}

// ---------------------------------------------------------------------------
// score_kernel: writes exp(S) fp16 (unnormalized) + atomic per-row exp-sums.
// 128 threads, 4 warps 2x2, warp 64x64.
// ---------------------------------------------------------------------------
#define SC_Q 0
#define SC_K 10240
#define SC_STAGE 20480
#define SC_SMEM (2 * SC_STAGE)

__global__ __launch_bounds__(128, 2) void score_kernel()
{
    extern __shared__ char sm[];
    const uint32_t uS = smem_u32(sm);

    const int tid = threadIdx.x;
    const int wid = tid >> 5, lid = tid & 31;
    const int m0 = blockIdx.x * 128;
    const int n0 = blockIdx.y * 128;
    const int b  = blockIdx.z;
    const size_t qbase = (size_t)(b * NS + m0) * ND;
    const size_t kbase = (size_t)(b * NS + n0) * ND;

    const int warpM = (wid >> 1) * 64;
    const int warpN = (wid & 1) * 64;
    const int a_row  = lid & 15;
    const int a_koff = (lid >> 4) * 8;
    const int bx_row  = (lid & 7) + (lid >> 4) * 8;
    const int bx_koff = ((lid >> 3) & 1) * 8;

    float acc[4][8][4];
    #pragma unroll
    for (int i = 0; i < 4; i++)
        #pragma unroll
        for (int j = 0; j < 8; j++)
            #pragma unroll
            for (int c = 0; c < 4; c++) acc[i][j][c] = 0.f;

    auto issue_stage = [&](int kc, int s) {
        const int k0 = kc * 32;
        const uint32_t base = uS + s * SC_STAGE;
        #pragma unroll
        for (int it = 0; it < 8; it++) {
            int f = tid + it * 128;
            int arr = f >> 9;
            int g = f & 511;
            int row = g >> 2, u = g & 3;
            const __half* src = (arr ? g_k + kbase : g_q + qbase) + (size_t)row * ND + k0 + u * 8;
            cp_async16(base + (arr ? SC_K : SC_Q) + (uint32_t)(row * BSTRIDE + u * 8) * 2, src);
        }
        CP_COMMIT();
    };

    issue_stage(0, 0);

    for (int kc = 0; kc < 4; kc++) {
        if (kc < 3) { issue_stage(kc + 1, (kc + 1) & 1); CP_WAIT(1); }
        else        { CP_WAIT(0); }
        __syncthreads();

        const uint32_t base = uS + (kc & 1) * SC_STAGE;
        #pragma unroll
        for (int ks = 0; ks < 2; ks++) {
            uint32_t ah[4][4];
            #pragma unroll
            for (int mi = 0; mi < 4; mi++) {
                uint32_t off = ((warpM + mi * 16 + a_row) * BSTRIDE + ks * 16 + a_koff) * 2;
                ldsm_x4(ah[mi], base + SC_Q + off);
            }
            #pragma unroll
            for (int njp = 0; njp < 4; njp++) {
                uint32_t boff = ((warpN + njp * 16 + bx_row) * BSTRIDE + ks * 16 + bx_koff) * 2;
                uint32_t bh[4];
                ldsm_x4(bh, base + SC_K + boff);
                #pragma unroll
                for (int h = 0; h < 2; h++)
                    #pragma unroll
                    for (int mi = 0; mi < 4; mi++)
                        mma16816(acc[mi][njp * 2 + h], ah[mi], &bh[h * 2]);
            }
        }
        __syncthreads();
    }

    // epilogue: exp -> fp16 scratch + row sums (shfl + atomic)
    __half* pe = g_pe + (size_t)b * NS * NS;
    #pragma unroll
    for (int mi = 0; mi < 4; mi++) {
        int r0 = m0 + warpM + mi * 16 + (lid >> 2);
        float rs0 = 0.f, rs1 = 0.f;
        #pragma unroll
        for (int nj = 0; nj < 8; nj++) {
            int c0 = n0 + warpN + nj * 8 + (lid & 3) * 2;
            float e0 = fast_exp(acc[mi][nj][0]);
            float e1 = fast_exp(acc[mi][nj][1]);
            float e2 = fast_exp(acc[mi][nj][2]);
            float e3 = fast_exp(acc[mi][nj][3]);
            *(uint32_t*)&pe[(size_t)r0 * NS + c0]       = pack_h2(e0, e1);
            *(uint32_t*)&pe[(size_t)(r0 + 8) * NS + c0] = pack_h2(e2, e3);
            rs0 += e0 + e1;
            rs1 += e2 + e3;
        }
        rs0 += __shfl_xor_sync(0xffffffffu, rs0, 1);
        rs0 += __shfl_xor_sync(0xffffffffu, rs0, 2);
        rs1 += __shfl_xor_sync(0xffffffffu, rs1, 1);
        rs1 += __shfl_xor_sync(0xffffffffu, rs1, 2);
        if ((lid & 3) == 0) {
            atomicAdd(&g_sums[b * NS + r0], rs0);
            atomicAdd(&g_sums[b * NS + r0 + 8], rs1);
        }
    }
}

// ---------------------------------------------------------------------------
// pv_kernel: O = (expS_fp16 @ V) * inv_sum; writes normalized fp32 probs.
// BM=64, grid(16,32)=512, 128 threads (4 warps 2x2, warp 32x64), 4 CTAs/SM.
// ---------------------------------------------------------------------------
#define PV_P   0                             // 64 x 40 fp16 = 5120 B
#define PV_V   5120                          // 32 x 136 fp16 = 8704 B
#define PV_STAGE 13824
#define PV_SMEM (2 * PV_STAGE)
#define VSTRIDE 136

__global__ __launch_bounds__(128, 4) void pv_kernel(float* __restrict__ probs,
                                                    float* __restrict__ o_out)
{
    extern __shared__ char sm[];
    __shared__ float s_inv[64];
    const uint32_t uS = smem_u32(sm);

    const int tid = threadIdx.x;
    const int wid = tid >> 5, lid = tid & 31;
    const int m0 = blockIdx.x * 64;
    const int b  = blockIdx.y;
    const size_t pbase = (size_t)(b * NS + m0) * NS;
    const size_t vbase = (size_t)(b * NS) * ND;

    const int warpM = (wid >> 1) * 32;       // 0, 32
    const int warpN = (wid & 1) * 64;        // 0, 64
    const int a_row  = lid & 15;
    const int a_koff = (lid >> 4) * 8;
    const int t_krow = (lid & 7) + ((lid >> 3) & 1) * 8;
    const int t_ncol = (lid >> 4) * 8;
    const int p_row = lid >> 2;

    if (tid < 64) s_inv[tid] = 1.0f / g_sums[b * NS + m0 + tid];

    float acc[2][8][4];
    #pragma unroll
    for (int i = 0; i < 2; i++)
        #pragma unroll
        for (int j = 0; j < 8; j++)
            #pragma unroll
            for (int c = 0; c < 4; c++) acc[i][j][c] = 0.f;

    auto issue_stage = [&](int kc, int s) {
        const int k0 = kc * 32;
        const uint32_t base = uS + s * PV_STAGE;
        // P: 64 rows x 32 fp16 = 256 cp16
        #pragma unroll
        for (int it = 0; it < 2; it++) {
            int f = tid + it * 128;
            int row = f >> 2, u = f & 3;
            const __half* src = g_pe + pbase + (size_t)row * NS + k0 + u * 8;
            cp_async16(base + PV_P + (uint32_t)(row * BSTRIDE + u * 8) * 2, src);
        }
        // V: 32 rows x 128 fp16 = 512 cp16
        #pragma unroll
        for (int it = 0; it < 4; it++) {
            int f = tid + it * 128;
            int row = f >> 4, u = f & 15;
            const __half* src = g_v + vbase + (size_t)(k0 + row) * ND + u * 8;
            cp_async16(base + PV_V + (uint32_t)(row * VSTRIDE + u * 8) * 2, src);
        }
        CP_COMMIT();
    };

    issue_stage(0, 0);
    __syncthreads();   // s_inv visible

    float inv0[2], inv1[2];
    #pragma unroll
    for (int mi = 0; mi < 2; mi++) {
        inv0[mi] = s_inv[warpM + mi * 16 + p_row];
        inv1[mi] = s_inv[warpM + mi * 16 + p_row + 8];
    }

    for (int kc = 0; kc < 32; kc++) {
        if (kc < 31) { issue_stage(kc + 1, (kc + 1) & 1); CP_WAIT(1); }
        else         { CP_WAIT(0); }
        __syncthreads();

        const uint32_t pb = uS + (kc & 1) * PV_STAGE;
        const char* stg = sm + (kc & 1) * PV_STAGE;
        const int k0c = kc * 32;

        #pragma unroll
        for (int ks = 0; ks < 2; ks++) {
            uint32_t ph[2][4];
            #pragma unroll
            for (int mi = 0; mi < 2; mi++) {
                uint32_t off = ((warpM + mi * 16 + a_row) * BSTRIDE + ks * 16 + a_koff) * 2;
                ldsm_x4(ph[mi], pb + PV_P + off);
            }
            #pragma unroll
            for (int njp = 0; njp < 4; njp++) {
                uint32_t toff = (uint32_t)((ks * 16 + t_krow) * VSTRIDE + warpN + njp * 16 + t_ncol) * 2;
                uint32_t vh[4];
                ldsm_x4_t(vh, pb + PV_V + toff);
                #pragma unroll
                for (int h = 0; h < 2; h++)
                    #pragma unroll
                    for (int mi = 0; mi < 2; mi++)
                        mma16816(acc[mi][njp * 2 + h], ph[mi], &vh[h * 2]);
            }
        }

        // write normalized fp32 probs chunk (from staged fp16 expS)
        #pragma unroll
        for (int it = 0; it < 2; it++) {
            int f = tid + it * 128;
            int row = f >> 2, u = f & 3;
            uint4 raw = *(const uint4*)(stg + PV_P + (uint32_t)(row * BSTRIDE + u * 8) * 2);
            float iv = s_inv[row];
            float2 a0 = __half22float2(*(__half2*)&raw.x);
            float2 a1 = __half22float2(*(__half2*)&raw.y);
            float2 a2 = __half22float2(*(__half2*)&raw.z);
            float2 a3 = __half22float2(*(__half2*)&raw.w);
            float4 o0 = make_float4(a0.x * iv, a0.y * iv, a1.x * iv, a1.y * iv);
            float4 o1 = make_float4(a2.x * iv, a2.y * iv, a3.x * iv, a3.y * iv);
            *(float4*)&probs[pbase + (size_t)row * NS + k0c + u * 8]     = o0;
            *(float4*)&probs[pbase + (size_t)row * NS + k0c + u * 8 + 4] = o1;
        }
        __syncthreads();
    }

    #pragma unroll
    for (int mi = 0; mi < 2; mi++) {
        #pragma unroll
        for (int nj = 0; nj < 8; nj++) {
            int r0 = m0 + warpM + mi * 16 + (lid >> 2);
            int c0 = warpN + nj * 8 + (lid & 3) * 2;
            *(float2*)&o_out[((size_t)(b * NS) + r0) * ND + c0] =
                make_float2(acc[mi][nj][0] * inv0[mi], acc[mi][nj][1] * inv0[mi]);
            *(float2*)&o_out[((size_t)(b * NS) + r0 + 8) * ND + c0] =
                make_float2(acc[mi][nj][2] * inv1[mi], acc[mi][nj][3] * inv1[mi]);
        }
    }
}

// ---------------------------------------------------------------------------
extern "C" void kernel_launch(void* const* d_in, const int* in_sizes, int n_in,
                              void* d_out, int out_size)
{
    const float* X  = (const float*)d_in[0];
    const float* Wq = (const float*)d_in[1];
    const float* bq = (const float*)d_in[2];
    const float* Wk = (const float*)d_in[3];
    const float* bk = (const float*)d_in[4];
    const float* Wv = (const float*)d_in[5];
    const float* bv = (const float*)d_in[6];

    float* out   = (float*)d_out;                 // [32,1024,128]
    float* probs = out + (size_t)NB * NS * ND;    // [32,1024,1024]

    cudaFuncSetAttribute(qkv_mma_kernel, cudaFuncAttributeMaxDynamicSharedMemorySize, QK_SMEM);
    cudaFuncSetAttribute(score_kernel, cudaFuncAttributeMaxDynamicSharedMemorySize, SC_SMEM);
    cudaFuncSetAttribute(pv_kernel, cudaFuncAttributeMaxDynamicSharedMemorySize, PV_SMEM);

    convw_kernel<<<48, 256>>>(Wq, Wk, Wv);
    qkv_mma_kernel<<<dim3(3, 256), 128, QK_SMEM>>>(X, bq, bk, bv);
    score_kernel<<<dim3(8, 8, 32), 128, SC_SMEM>>>();
    pv_kernel<<<dim3(16, 32), 128, PV_SMEM>>>(probs, out);
}